// round 7
// baseline (speedup 1.0000x reference)
#include <cuda_runtime.h>
#include <cuda_bf16.h>
#include <math.h>

#define BB   128
#define NTOK 1000
#define NPAD 1024
#define EE   128
#define HH   8
#define NEGV (-1000000000.0f)
#define SCALE 0.25f

// K, V, G oct-interleaved over feature: (b,e,n) -> bf16
//   ((b*16 + (e>>3)) * NPAD + n) * 8 + (e&7)
// i.e. per (b, oct) a row of NPAD uint4 entries (one uint4 = 8 features of one token).
__device__ uint4 g_K8[BB * 16 * NPAD];
__device__ uint4 g_V8[BB * 16 * NPAD];
__device__ uint4 g_G8[BB * 16 * NPAD];
__device__ __nv_bfloat16 g_LKp[BB * EE * NPAD];
__device__ float g_SK   [(size_t)BB * NTOK * EE];   // node @ Wstep[128:]
__device__ float g_qbase[BB * EE];
__device__ float g_blk  [BB * NPAD];                // bmlp . LK[:,n]

// ---------------------------------------------------------------------------
// Precompute 1: qkv = node @ Wqkv + bqkv -> K8 / V8 / LKp
// ---------------------------------------------------------------------------
__global__ void qkv_gemm(const float* __restrict__ node,
                         const float* __restrict__ W,
                         const float* __restrict__ bias) {
    __shared__ float As[16][64];
    __shared__ float Bs[16][64];
    const int b  = blockIdx.z;
    const int n0 = blockIdx.y * 64;
    const int e0 = blockIdx.x * 64;
    const int tx = threadIdx.x, ty = threadIdx.y;
    const int t  = ty * 16 + tx;
    const int an = t >> 2, ak = (t & 3) * 4;
    const int bk = t >> 4, be = (t & 15) * 4;

    float acc[4][4] = {};
    for (int k0 = 0; k0 < 128; k0 += 16) {
        float4 av;
        const int n = n0 + an;
        if (n < NTOK) av = *(const float4*)&node[((size_t)b * NTOK + n) * EE + k0 + ak];
        else          av = make_float4(0.f, 0.f, 0.f, 0.f);
        As[ak + 0][an] = av.x; As[ak + 1][an] = av.y;
        As[ak + 2][an] = av.z; As[ak + 3][an] = av.w;
        *(float4*)&Bs[bk][be] = *(const float4*)&W[(size_t)(k0 + bk) * 384 + e0 + be];
        __syncthreads();
        #pragma unroll
        for (int kk = 0; kk < 16; ++kk) {
            float ar[4], br[4];
            #pragma unroll
            for (int i = 0; i < 4; ++i) ar[i] = As[kk][ty * 4 + i];
            #pragma unroll
            for (int j = 0; j < 4; ++j) br[j] = Bs[kk][tx * 4 + j];
            #pragma unroll
            for (int i = 0; i < 4; ++i)
                #pragma unroll
                for (int j = 0; j < 4; ++j) acc[i][j] += ar[i] * br[j];
        }
        __syncthreads();
    }

    __nv_bfloat16* K = (__nv_bfloat16*)g_K8;
    __nv_bfloat16* V = (__nv_bfloat16*)g_V8;
    #pragma unroll
    for (int i = 0; i < 4; ++i) {
        const int n = n0 + ty * 4 + i;
        if (n >= NTOK) continue;
        #pragma unroll
        for (int j = 0; j < 4; ++j) {
            const int e3 = e0 + tx * 4 + j;
            const __nv_bfloat16 bv = __float2bfloat16(acc[i][j] + bias[e3]);
            if (e3 < 128) {
                const int e = e3;
                K[((size_t)(b * 16 + (e >> 3)) * NPAD + n) * 8 + (e & 7)] = bv;
            } else if (e3 < 256) {
                const int e = e3 - 128;
                V[((size_t)(b * 16 + (e >> 3)) * NPAD + n) * 8 + (e & 7)] = bv;
            } else {
                const int e = e3 - 256;
                g_LKp[(size_t)(b * EE + e) * NPAD + n] = bv;
            }
        }
    }
}

// ---------------------------------------------------------------------------
// Precompute 2: SK[b][n][e] = node[b,n] @ Wstep[128:256]  (fp32)
// ---------------------------------------------------------------------------
__global__ void sk_gemm(const float* __restrict__ node,
                        const float* __restrict__ Wstep) {
    __shared__ float As[16][64];
    __shared__ float Bs[16][64];
    const float* W2 = Wstep + 128 * EE;
    const int b  = blockIdx.z;
    const int n0 = blockIdx.y * 64;
    const int e0 = blockIdx.x * 64;
    const int tx = threadIdx.x, ty = threadIdx.y;
    const int t  = ty * 16 + tx;
    const int an = t >> 2, ak = (t & 3) * 4;
    const int bk = t >> 4, be = (t & 15) * 4;

    float acc[4][4] = {};
    for (int k0 = 0; k0 < 128; k0 += 16) {
        float4 av;
        const int n = n0 + an;
        if (n < NTOK) av = *(const float4*)&node[((size_t)b * NTOK + n) * EE + k0 + ak];
        else          av = make_float4(0.f, 0.f, 0.f, 0.f);
        As[ak + 0][an] = av.x; As[ak + 1][an] = av.y;
        As[ak + 2][an] = av.z; As[ak + 3][an] = av.w;
        *(float4*)&Bs[bk][be] = *(const float4*)&W2[(size_t)(k0 + bk) * EE + e0 + be];
        __syncthreads();
        #pragma unroll
        for (int kk = 0; kk < 16; ++kk) {
            float ar[4], br[4];
            #pragma unroll
            for (int i = 0; i < 4; ++i) ar[i] = As[kk][ty * 4 + i];
            #pragma unroll
            for (int j = 0; j < 4; ++j) br[j] = Bs[kk][tx * 4 + j];
            #pragma unroll
            for (int i = 0; i < 4; ++i)
                #pragma unroll
                for (int j = 0; j < 4; ++j) acc[i][j] += ar[i] * br[j];
        }
        __syncthreads();
    }
    #pragma unroll
    for (int i = 0; i < 4; ++i) {
        const int n = n0 + ty * 4 + i;
        if (n >= NTOK) continue;
        #pragma unroll
        for (int j = 0; j < 4; ++j)
            g_SK[((size_t)b * NTOK + n) * EE + e0 + tx * 4 + j] = acc[i][j];
    }
}

// ---------------------------------------------------------------------------
// Precompute 3: G[b][c][n] = Wmlp[c][:] . LK[b][:][n]  -> oct-interleaved bf16
// ---------------------------------------------------------------------------
__global__ void g_gemm(const float* __restrict__ Wmlp) {
    __shared__ float As[16][64];   // [e][c]
    __shared__ float Bs[16][64];   // [e][n]
    const int b  = blockIdx.z;
    const int n0 = blockIdx.y * 64;
    const int c0 = blockIdx.x * 64;
    const int tx = threadIdx.x, ty = threadIdx.y;
    const int t  = ty * 16 + tx;
    const int ac = t >> 2, ae = (t & 3) * 4;
    const int bk = t >> 4, bn = (t & 15) * 4;

    float acc[4][4] = {};
    for (int k0 = 0; k0 < 128; k0 += 16) {
        const float4 av = *(const float4*)&Wmlp[(size_t)(c0 + ac) * EE + k0 + ae];
        As[ae + 0][ac] = av.x; As[ae + 1][ac] = av.y;
        As[ae + 2][ac] = av.z; As[ae + 3][ac] = av.w;
        const uint2 r = *(const uint2*)&g_LKp[(size_t)(b * EE + k0 + bk) * NPAD + n0 + bn];
        const float2 v0 = __bfloat1622float2(*(const __nv_bfloat162*)&r.x);
        const float2 v1 = __bfloat1622float2(*(const __nv_bfloat162*)&r.y);
        Bs[bk][bn + 0] = v0.x; Bs[bk][bn + 1] = v0.y;
        Bs[bk][bn + 2] = v1.x; Bs[bk][bn + 3] = v1.y;
        __syncthreads();
        #pragma unroll
        for (int kk = 0; kk < 16; ++kk) {
            float ar[4], br[4];
            #pragma unroll
            for (int i = 0; i < 4; ++i) ar[i] = As[kk][ty * 4 + i];
            #pragma unroll
            for (int j = 0; j < 4; ++j) br[j] = Bs[kk][tx * 4 + j];
            #pragma unroll
            for (int i = 0; i < 4; ++i)
                #pragma unroll
                for (int j = 0; j < 4; ++j) acc[i][j] += ar[i] * br[j];
        }
        __syncthreads();
    }
    __nv_bfloat16* G = (__nv_bfloat16*)g_G8;
    #pragma unroll
    for (int i = 0; i < 4; ++i) {
        const int c = c0 + ty * 4 + i;
        #pragma unroll
        for (int j = 0; j < 4; ++j) {
            const int n = n0 + tx * 4 + j;
            G[((size_t)(b * 16 + (c >> 3)) * NPAD + n) * 8 + (c & 7)] =
                __float2bfloat16(acc[i][j]);
        }
    }
}

// ---------------------------------------------------------------------------
// Precompute 4: blk[b][n] = bmlp . LK[b][:][n]
// ---------------------------------------------------------------------------
__global__ void blk_kernel(const float* __restrict__ bmlp) {
    const int b = blockIdx.x, n = threadIdx.x;
    __shared__ float bm[EE];
    if (n < EE) bm[n] = bmlp[n];
    __syncthreads();
    float a = 0.f;
    #pragma unroll 8
    for (int e = 0; e < EE; ++e)
        a += bm[e] * __bfloat162float(g_LKp[(size_t)(b * EE + e) * NPAD + n]);
    g_blk[b * NPAD + n] = a;
}

// ---------------------------------------------------------------------------
// Precompute 5: qbase = graph@Wfix + bfix + bstep + first@Wstep[:128]
// ---------------------------------------------------------------------------
__global__ void qbase_kernel(const float* __restrict__ g,
                             const float* __restrict__ node,
                             const float* __restrict__ Wfix,
                             const float* __restrict__ bfix,
                             const float* __restrict__ Wstep,
                             const float* __restrict__ bstep) {
    const int b = blockIdx.x, e = threadIdx.x;
    __shared__ float gs[EE], fs[EE];
    gs[e] = g[b * EE + e];
    fs[e] = node[(size_t)b * NTOK * EE + e];
    __syncthreads();
    float a = bfix[e] + bstep[e];
    #pragma unroll 4
    for (int k = 0; k < EE; ++k) {
        a += gs[k] * Wfix[(size_t)k * EE + e];
        a += fs[k] * Wstep[(size_t)k * EE + e];
    }
    g_qbase[b * EE + e] = a;
}

__device__ __forceinline__ float tanh_fast(float x) {
    float r;
    asm("tanh.approx.f32 %0, %1;" : "=f"(r) : "f"(x));
    return r;
}

// dot of 8 bf16 (uint4) with 8 fp32 from aligned smem
__device__ __forceinline__ float dot8(const uint4 r, const float* __restrict__ q) {
    const float2 f0 = __bfloat1622float2(*(const __nv_bfloat162*)&r.x);
    const float2 f1 = __bfloat1622float2(*(const __nv_bfloat162*)&r.y);
    const float2 f2 = __bfloat1622float2(*(const __nv_bfloat162*)&r.z);
    const float2 f3 = __bfloat1622float2(*(const __nv_bfloat162*)&r.w);
    const float4 q0 = *(const float4*)q;
    const float4 q1 = *(const float4*)(q + 4);
    return q0.x * f0.x + q0.y * f0.y + q0.z * f1.x + q0.w * f1.y
         + q1.x * f2.x + q1.y * f2.y + q1.z * f3.x + q1.w * f3.y;
}

// ---------------------------------------------------------------------------
// Persistent decode loop with periodic active-token compaction.
// ---------------------------------------------------------------------------
__global__ void __launch_bounds__(1024, 1)
decode_loop(float* __restrict__ out) {
    const int b    = blockIdx.x;
    const int t    = threadIdx.x;
    const int warp = t >> 5, lane = t & 31;

    __shared__ __align__(16) float smp[HH * NPAD];   // 32 KB
    __shared__ float sm_blk[NPAD];                   // 4 KB
    __shared__ int   sm_idx[NPAD];                   // 4 KB: compact slot -> original n
    __shared__ float sm_wred[32 * 9];
    __shared__ int   sm_iwred[32];
    __shared__ __align__(16) float sm_q[EE];
    __shared__ __align__(16) float sm_ctx[EE];
    __shared__ float sm_qbase[EE];
    __shared__ unsigned char sm_mask[NPAD];
    __shared__ int   sm_cbase[32];
    __shared__ int   sm_newM;

    if (t < EE) sm_qbase[t] = g_qbase[b * EE + t];
    sm_blk[t]  = g_blk[b * NPAD + t];
    sm_idx[t]  = t;
    sm_mask[t] = (t == 0 || t >= NTOK) ? 1 : 0;
    __syncthreads();

    const uint4* kq = g_K8 + (size_t)b * 16 * NPAD;   // + oct*NPAD + token
    const uint4* gq = g_G8 + (size_t)b * 16 * NPAD;
    int   cur   = 0;       // original index of last selected node
    float total = 0.f;
    int   M_pad = NPAD;    // active slots (rounded to 32)
    int   nch   = NPAD / 32;

    #pragma unroll 1
    for (int step = 0; step < NTOK - 1; ++step) {
        // ---- q row: qbase + SK[cur] ----
        if (t < EE)
            sm_q[t] = sm_qbase[t] + g_SK[((size_t)b * NTOK + cur) * EE + t];
        __syncthreads();   // S1 (publishes mask update / compaction from prev iter)

        // ---- C: scores, p = exp (no max-shift), per-warp head sums ----
        const bool msk = sm_mask[t];
        if (t < M_pad) {
            #pragma unroll
            for (int h = 0; h < HH; ++h) {
                const float a = dot8(kq[(size_t)(2 * h)     * NPAD + t], &sm_q[h * 16])
                              + dot8(kq[(size_t)(2 * h + 1) * NPAD + t], &sm_q[h * 16 + 8]);
                float p = msk ? 0.f : __expf(a * SCALE);
                smp[h * NPAD + t] = p;
                #pragma unroll
                for (int o = 16; o > 0; o >>= 1)
                    p += __shfl_xor_sync(~0u, p, o);
                if (lane == 0) sm_wred[warp * 9 + h] = p;
            }
        } else if (lane == 0) {
            #pragma unroll
            for (int h = 0; h < HH; ++h) sm_wred[warp * 9 + h] = 0.f;
        }
        __syncthreads();   // S2

        // ---- D: ctx; warp w < 16 owns feature oct w (e = 8w..8w+7), h = w>>1 ----
        if (warp < 16) {
            const int h = warp >> 1;
            float sv = sm_wred[lane * 9 + h];
            #pragma unroll
            for (int o = 16; o > 0; o >>= 1)
                sv += __shfl_xor_sync(~0u, sv, o);
            const float inv = 1.0f / sv;
            float a0 = 0.f, a1 = 0.f, a2 = 0.f, a3 = 0.f;
            float a4 = 0.f, a5 = 0.f, a6 = 0.f, a7 = 0.f;
            const uint4* vt = g_V8 + ((size_t)b * 16 + warp) * NPAD;
            const float* pp = smp + h * NPAD;
            #pragma unroll 2
            for (int n = lane; n < M_pad; n += 32) {
                const uint4 r = vt[n];
                const float p = pp[n];
                const float2 f0 = __bfloat1622float2(*(const __nv_bfloat162*)&r.x);
                const float2 f1 = __bfloat1622float2(*(const __nv_bfloat162*)&r.y);
                const float2 f2 = __bfloat1622float2(*(const __nv_bfloat162*)&r.z);
                const float2 f3 = __bfloat1622float2(*(const __nv_bfloat162*)&r.w);
                a0 += p * f0.x; a1 += p * f0.y; a2 += p * f1.x; a3 += p * f1.y;
                a4 += p * f2.x; a5 += p * f2.y; a6 += p * f3.x; a7 += p * f3.y;
            }
            #pragma unroll
            for (int o = 16; o > 0; o >>= 1) {
                a0 += __shfl_xor_sync(~0u, a0, o);
                a1 += __shfl_xor_sync(~0u, a1, o);
                a2 += __shfl_xor_sync(~0u, a2, o);
                a3 += __shfl_xor_sync(~0u, a3, o);
                a4 += __shfl_xor_sync(~0u, a4, o);
                a5 += __shfl_xor_sync(~0u, a5, o);
                a6 += __shfl_xor_sync(~0u, a6, o);
                a7 += __shfl_xor_sync(~0u, a7, o);
            }
            if (lane == 0) {
                float* c = sm_ctx + warp * 8;
                c[0] = a0 * inv; c[1] = a1 * inv; c[2] = a2 * inv; c[3] = a3 * inv;
                c[4] = a4 * inv; c[5] = a5 * inv; c[6] = a6 * inv; c[7] = a7 * inv;
            }
        }
        __syncthreads();   // S3

        // ---- F: logits = ctx.G + blk; fused argmax + sum exp ----
        {
            float mv = NEGV, s = 0.f;
            int   mi = t;
            if (t < M_pad) {
                float a = sm_blk[t];
                #pragma unroll
                for (int o8 = 0; o8 < 16; ++o8)
                    a += dot8(gq[(size_t)o8 * NPAD + t], &sm_ctx[o8 * 8]);
                if (!msk) {
                    mv = a;
                    s  = __expf(tanh_fast(a * SCALE) * 10.0f);
                }
                #pragma unroll
                for (int o = 16; o > 0; o >>= 1) {
                    const float ov = __shfl_xor_sync(~0u, mv, o);
                    const int   oi = __shfl_xor_sync(~0u, mi, o);
                    s += __shfl_xor_sync(~0u, s, o);
                    if (ov > mv || (ov == mv && oi < mi)) { mv = ov; mi = oi; }
                }
            }
            if (lane == 0) {
                sm_wred[warp * 9 + 0] = mv;
                sm_wred[warp * 9 + 1] = s;
                sm_iwred[warp] = mi;
            }
        }
        __syncthreads();   // S4

        // ---- final reduce, redundant in every warp ----
        {
            float mv = sm_wred[lane * 9 + 0];
            float s  = sm_wred[lane * 9 + 1];
            int   mi = sm_iwred[lane];
            #pragma unroll
            for (int o = 16; o > 0; o >>= 1) {
                const float ov = __shfl_xor_sync(~0u, mv, o);
                const int   oi = __shfl_xor_sync(~0u, mi, o);
                s += __shfl_xor_sync(~0u, s, o);
                if (ov > mv || (ov == mv && oi < mi)) { mv = ov; mi = oi; }
            }
            if (t == 0) {
                total += tanhf(mv * SCALE) * 10.0f - logf(s);  // precise winner
                sm_mask[mi] = 1;
            }
            cur = sm_idx[mi];   // original index (broadcast LDS)
        }

        // ---- periodic stable compaction of active tokens ----
        if (((step + 1) & 63) == 0) {
            __syncthreads();                 // CS1: mask/idx reads done, mask final
            if (warp == 0) {
                int cnt = 0;
                if (lane < nch) {
                    const unsigned char* mp = sm_mask + lane * 32;
                    #pragma unroll
                    for (int j = 0; j < 32; ++j) cnt += (mp[j] == 0);
                }
                int inc = cnt;
                #pragma unroll
                for (int o = 1; o < 32; o <<= 1) {
                    const int v = __shfl_up_sync(~0u, inc, o);
                    if (lane >= o) inc += v;
                }
                if (lane < nch) sm_cbase[lane] = inc - cnt;
                if (lane == nch - 1) sm_newM = inc;
            }
            __syncthreads();                 // CS2
            {
                // 48 (array, oct) rows over 32 warps
                for (int rr = warp; rr < 48; rr += 32) {
                    uint4* row = (rr < 16 ? g_K8 : rr < 32 ? g_V8 : g_G8)
                               + ((size_t)b * 16 + (rr & 15)) * NPAD;
                    for (int c = 0; c < nch; ++c) {
                        const int n = c * 32 + lane;
                        const uint4 v = row[n];
                        const bool keep = (sm_mask[n] == 0);
                        const unsigned bal = __ballot_sync(~0u, keep);
                        if (keep)
                            row[sm_cbase[c] + __popc(bal & ((1u << lane) - 1))] = v;
                    }
                }
                if (warp == 30) {            // compact blk (smem, in-place)
                    for (int c = 0; c < nch; ++c) {
                        const int n = c * 32 + lane;
                        const float v = sm_blk[n];
                        const bool keep = (sm_mask[n] == 0);
                        const unsigned bal = __ballot_sync(~0u, keep);
                        if (keep)
                            sm_blk[sm_cbase[c] + __popc(bal & ((1u << lane) - 1))] = v;
                    }
                }
                if (warp == 31) {            // compact idx map
                    for (int c = 0; c < nch; ++c) {
                        const int n = c * 32 + lane;
                        const int v = sm_idx[n];
                        const bool keep = (sm_mask[n] == 0);
                        const unsigned bal = __ballot_sync(~0u, keep);
                        if (keep)
                            sm_idx[sm_cbase[c] + __popc(bal & ((1u << lane) - 1))] = v;
                    }
                }
            }
            __syncthreads();                 // CS3: moves done
            const int M = sm_newM;
            M_pad = (M + 31) & ~31;
            nch   = M_pad >> 5;
            sm_mask[t] = (t >= M) ? 1 : 0;   // all active slots unmasked
            // next S1 publishes before any read
        }
    }

    if (t == 0) out[b] = total;
}

// ---------------------------------------------------------------------------
extern "C" void kernel_launch(void* const* d_in, const int* in_sizes, int n_in,
                              void* d_out, int out_size) {
    const float* node  = (const float*)d_in[0];
    const float* graph = (const float*)d_in[1];
    const float* Wqkv  = (const float*)d_in[2];
    const float* bqkv  = (const float*)d_in[3];
    const float* Wfix  = (const float*)d_in[4];
    const float* bfix  = (const float*)d_in[5];
    const float* Wstep = (const float*)d_in[6];
    const float* bstep = (const float*)d_in[7];
    const float* Wmlp  = (const float*)d_in[8];
    const float* bmlp  = (const float*)d_in[9];
    float* out = (float*)d_out;

    dim3 blk2(16, 16);
    qkv_gemm<<<dim3(6, 16, BB), blk2>>>(node, Wqkv, bqkv);
    sk_gemm <<<dim3(2, 16, BB), blk2>>>(node, Wstep);
    g_gemm  <<<dim3(2, 16, BB), blk2>>>(Wmlp);
    blk_kernel <<<BB, NPAD>>>(bmlp);
    qbase_kernel<<<BB, EE>>>(graph, node, Wfix, bfix, Wstep, bstep);
    decode_loop<<<BB, 1024>>>(out);
}

// round 8
// speedup vs baseline: 1.2208x; 1.2208x over previous
#include <cuda_runtime.h>
#include <cuda_bf16.h>
#include <math.h>

#define BB   128
#define NTOK 1000
#define NPAD 1024
#define EE   128
#define HH   8
#define NEGV (-1000000000.0f)
#define SCALE 0.25f

// K, V, G quad-interleaved over feature: (b,e,n) -> bf16
//   ((b*32 + (e>>2)) * NPAD + n) * 4 + (e&3)
__device__ uint2 g_K4[BB * 32 * NPAD];
__device__ uint2 g_V4[BB * 32 * NPAD];
__device__ uint2 g_G4[BB * 32 * NPAD];
__device__ __nv_bfloat16 g_LKp[BB * EE * NPAD];
__device__ float g_SK   [(size_t)BB * NTOK * EE];   // node @ Wstep[128:]
__device__ float g_qbase[BB * EE];
__device__ float g_blk  [BB * NPAD];                // bmlp . LK[:,n]

// ---------------------------------------------------------------------------
// Precompute 1: qkv = node @ Wqkv + bqkv -> K4 / V4 / LKp
// ---------------------------------------------------------------------------
__global__ void qkv_gemm(const float* __restrict__ node,
                         const float* __restrict__ W,
                         const float* __restrict__ bias) {
    __shared__ float As[16][64];
    __shared__ float Bs[16][64];
    const int b  = blockIdx.z;
    const int n0 = blockIdx.y * 64;
    const int e0 = blockIdx.x * 64;
    const int tx = threadIdx.x, ty = threadIdx.y;
    const int t  = ty * 16 + tx;
    const int an = t >> 2, ak = (t & 3) * 4;
    const int bk = t >> 4, be = (t & 15) * 4;

    float acc[4][4] = {};
    for (int k0 = 0; k0 < 128; k0 += 16) {
        float4 av;
        const int n = n0 + an;
        if (n < NTOK) av = *(const float4*)&node[((size_t)b * NTOK + n) * EE + k0 + ak];
        else          av = make_float4(0.f, 0.f, 0.f, 0.f);
        As[ak + 0][an] = av.x; As[ak + 1][an] = av.y;
        As[ak + 2][an] = av.z; As[ak + 3][an] = av.w;
        *(float4*)&Bs[bk][be] = *(const float4*)&W[(size_t)(k0 + bk) * 384 + e0 + be];
        __syncthreads();
        #pragma unroll
        for (int kk = 0; kk < 16; ++kk) {
            float ar[4], br[4];
            #pragma unroll
            for (int i = 0; i < 4; ++i) ar[i] = As[kk][ty * 4 + i];
            #pragma unroll
            for (int j = 0; j < 4; ++j) br[j] = Bs[kk][tx * 4 + j];
            #pragma unroll
            for (int i = 0; i < 4; ++i)
                #pragma unroll
                for (int j = 0; j < 4; ++j) acc[i][j] += ar[i] * br[j];
        }
        __syncthreads();
    }

    __nv_bfloat16* K = (__nv_bfloat16*)g_K4;
    __nv_bfloat16* V = (__nv_bfloat16*)g_V4;
    #pragma unroll
    for (int i = 0; i < 4; ++i) {
        const int n = n0 + ty * 4 + i;
        if (n >= NTOK) continue;
        #pragma unroll
        for (int j = 0; j < 4; ++j) {
            const int e3 = e0 + tx * 4 + j;
            const __nv_bfloat16 bv = __float2bfloat16(acc[i][j] + bias[e3]);
            if (e3 < 128) {
                const int e = e3;
                K[((size_t)(b * 32 + (e >> 2)) * NPAD + n) * 4 + (e & 3)] = bv;
            } else if (e3 < 256) {
                const int e = e3 - 128;
                V[((size_t)(b * 32 + (e >> 2)) * NPAD + n) * 4 + (e & 3)] = bv;
            } else {
                const int e = e3 - 256;
                g_LKp[(size_t)(b * EE + e) * NPAD + n] = bv;
            }
        }
    }
}

// ---------------------------------------------------------------------------
// Precompute 2: SK[b][n][e] = node[b,n] @ Wstep[128:256]  (fp32)
// ---------------------------------------------------------------------------
__global__ void sk_gemm(const float* __restrict__ node,
                        const float* __restrict__ Wstep) {
    __shared__ float As[16][64];
    __shared__ float Bs[16][64];
    const float* W2 = Wstep + 128 * EE;
    const int b  = blockIdx.z;
    const int n0 = blockIdx.y * 64;
    const int e0 = blockIdx.x * 64;
    const int tx = threadIdx.x, ty = threadIdx.y;
    const int t  = ty * 16 + tx;
    const int an = t >> 2, ak = (t & 3) * 4;
    const int bk = t >> 4, be = (t & 15) * 4;

    float acc[4][4] = {};
    for (int k0 = 0; k0 < 128; k0 += 16) {
        float4 av;
        const int n = n0 + an;
        if (n < NTOK) av = *(const float4*)&node[((size_t)b * NTOK + n) * EE + k0 + ak];
        else          av = make_float4(0.f, 0.f, 0.f, 0.f);
        As[ak + 0][an] = av.x; As[ak + 1][an] = av.y;
        As[ak + 2][an] = av.z; As[ak + 3][an] = av.w;
        *(float4*)&Bs[bk][be] = *(const float4*)&W2[(size_t)(k0 + bk) * EE + e0 + be];
        __syncthreads();
        #pragma unroll
        for (int kk = 0; kk < 16; ++kk) {
            float ar[4], br[4];
            #pragma unroll
            for (int i = 0; i < 4; ++i) ar[i] = As[kk][ty * 4 + i];
            #pragma unroll
            for (int j = 0; j < 4; ++j) br[j] = Bs[kk][tx * 4 + j];
            #pragma unroll
            for (int i = 0; i < 4; ++i)
                #pragma unroll
                for (int j = 0; j < 4; ++j) acc[i][j] += ar[i] * br[j];
        }
        __syncthreads();
    }
    #pragma unroll
    for (int i = 0; i < 4; ++i) {
        const int n = n0 + ty * 4 + i;
        if (n >= NTOK) continue;
        #pragma unroll
        for (int j = 0; j < 4; ++j)
            g_SK[((size_t)b * NTOK + n) * EE + e0 + tx * 4 + j] = acc[i][j];
    }
}

// ---------------------------------------------------------------------------
// Precompute 3: G[b][c][n] = Wmlp[c][:] . LK[b][:][n]  -> quad-interleaved bf16
// ---------------------------------------------------------------------------
__global__ void g_gemm(const float* __restrict__ Wmlp) {
    __shared__ float As[16][64];   // [e][c]
    __shared__ float Bs[16][64];   // [e][n]
    const int b  = blockIdx.z;
    const int n0 = blockIdx.y * 64;
    const int c0 = blockIdx.x * 64;
    const int tx = threadIdx.x, ty = threadIdx.y;
    const int t  = ty * 16 + tx;
    const int ac = t >> 2, ae = (t & 3) * 4;
    const int bk = t >> 4, bn = (t & 15) * 4;

    float acc[4][4] = {};
    for (int k0 = 0; k0 < 128; k0 += 16) {
        const float4 av = *(const float4*)&Wmlp[(size_t)(c0 + ac) * EE + k0 + ae];
        As[ae + 0][ac] = av.x; As[ae + 1][ac] = av.y;
        As[ae + 2][ac] = av.z; As[ae + 3][ac] = av.w;
        const uint2 r = *(const uint2*)&g_LKp[(size_t)(b * EE + k0 + bk) * NPAD + n0 + bn];
        const float2 v0 = __bfloat1622float2(*(const __nv_bfloat162*)&r.x);
        const float2 v1 = __bfloat1622float2(*(const __nv_bfloat162*)&r.y);
        Bs[bk][bn + 0] = v0.x; Bs[bk][bn + 1] = v0.y;
        Bs[bk][bn + 2] = v1.x; Bs[bk][bn + 3] = v1.y;
        __syncthreads();
        #pragma unroll
        for (int kk = 0; kk < 16; ++kk) {
            float ar[4], br[4];
            #pragma unroll
            for (int i = 0; i < 4; ++i) ar[i] = As[kk][ty * 4 + i];
            #pragma unroll
            for (int j = 0; j < 4; ++j) br[j] = Bs[kk][tx * 4 + j];
            #pragma unroll
            for (int i = 0; i < 4; ++i)
                #pragma unroll
                for (int j = 0; j < 4; ++j) acc[i][j] += ar[i] * br[j];
        }
        __syncthreads();
    }
    __nv_bfloat16* G = (__nv_bfloat16*)g_G4;
    #pragma unroll
    for (int i = 0; i < 4; ++i) {
        const int c = c0 + ty * 4 + i;
        #pragma unroll
        for (int j = 0; j < 4; ++j) {
            const int n = n0 + tx * 4 + j;
            G[((size_t)(b * 32 + (c >> 2)) * NPAD + n) * 4 + (c & 3)] =
                __float2bfloat16(acc[i][j]);
        }
    }
}

// ---------------------------------------------------------------------------
// Precompute 4: blk[b][n] = bmlp . LK[b][:][n]
// ---------------------------------------------------------------------------
__global__ void blk_kernel(const float* __restrict__ bmlp) {
    const int b = blockIdx.x, n = threadIdx.x;
    __shared__ float bm[EE];
    if (n < EE) bm[n] = bmlp[n];
    __syncthreads();
    float a = 0.f;
    #pragma unroll 8
    for (int e = 0; e < EE; ++e)
        a += bm[e] * __bfloat162float(g_LKp[(size_t)(b * EE + e) * NPAD + n]);
    g_blk[b * NPAD + n] = a;
}

// ---------------------------------------------------------------------------
// Precompute 5: qbase = graph@Wfix + bfix + bstep + first@Wstep[:128]
// ---------------------------------------------------------------------------
__global__ void qbase_kernel(const float* __restrict__ g,
                             const float* __restrict__ node,
                             const float* __restrict__ Wfix,
                             const float* __restrict__ bfix,
                             const float* __restrict__ Wstep,
                             const float* __restrict__ bstep) {
    const int b = blockIdx.x, e = threadIdx.x;
    __shared__ float gs[EE], fs[EE];
    gs[e] = g[b * EE + e];
    fs[e] = node[(size_t)b * NTOK * EE + e];
    __syncthreads();
    float a = bfix[e] + bstep[e];
    #pragma unroll 4
    for (int k = 0; k < EE; ++k) {
        a += gs[k] * Wfix[(size_t)k * EE + e];
        a += fs[k] * Wstep[(size_t)k * EE + e];
    }
    g_qbase[b * EE + e] = a;
}

__device__ __forceinline__ float tanh_fast(float x) {
    float r;
    asm("tanh.approx.f32 %0, %1;" : "=f"(r) : "f"(x));
    return r;
}

// ---------------------------------------------------------------------------
// Persistent decode loop with periodic active-token compaction.
// ---------------------------------------------------------------------------
__global__ void __launch_bounds__(1024, 1)
decode_loop(float* __restrict__ out) {
    const int b    = blockIdx.x;
    const int t    = threadIdx.x;
    const int warp = t >> 5, lane = t & 31;

    __shared__ __align__(16) float smp[HH * NPAD];   // 32 KB
    __shared__ float sm_blk[NPAD];                   // 4 KB
    __shared__ int   sm_idx[NPAD];                   // 4 KB
    __shared__ float sm_wred[32 * 9];
    __shared__ int   sm_iwred[32];
    __shared__ __align__(16) float sm_q[EE];
    __shared__ __align__(16) float sm_ctx[EE];
    __shared__ float sm_qbase[EE];
    __shared__ unsigned char sm_mask[NPAD];
    __shared__ int   sm_cbase[32];
    __shared__ int   sm_newM;

    if (t < EE) sm_qbase[t] = g_qbase[b * EE + t];
    sm_blk[t]  = g_blk[b * NPAD + t];
    sm_idx[t]  = t;
    sm_mask[t] = (t == 0 || t >= NTOK) ? 1 : 0;
    __syncthreads();

    const uint2* kq = g_K4 + (size_t)b * 32 * NPAD + t;
    const uint2* gq = g_G4 + (size_t)b * 32 * NPAD + t;
    int   cur   = 0;
    float total = 0.f;
    int   M_pad = NPAD;    // active slots (rounded to 32)
    int   nch   = NPAD / 32;

    #pragma unroll 1
    for (int step = 0; step < NTOK - 1; ++step) {
        // ---- q row: qbase + SK[cur] ----
        if (t < EE)
            sm_q[t] = sm_qbase[t] + g_SK[((size_t)b * NTOK + cur) * EE + t];
        __syncthreads();   // S1 (publishes q + mask/compaction from prev iter)

        // ---- C: scores, p = exp (no max-shift); NO reduction here ----
        const bool msk = sm_mask[t];
        if (t < M_pad) {
            #pragma unroll
            for (int h = 0; h < HH; ++h) {
                float a = 0.f;
                #pragma unroll
                for (int c = 0; c < 4; ++c) {
                    const uint2 r = kq[(size_t)(4 * h + c) * NPAD];
                    const float2 k0 = __bfloat1622float2(*(const __nv_bfloat162*)&r.x);
                    const float2 k1 = __bfloat1622float2(*(const __nv_bfloat162*)&r.y);
                    const float4 qv = *(const float4*)&sm_q[h * 16 + 4 * c];
                    a += qv.x * k0.x + qv.y * k0.y + qv.z * k1.x + qv.w * k1.y;
                }
                smp[h * NPAD + t] = msk ? 0.f : __expf(a * SCALE);
            }
        }
        __syncthreads();   // S2

        // ---- D: ctx; warp w owns quad w (e = 4w..4w+3), h = w>>2;
        //      per-head softmax sum folded into this loop (free FADD) ----
        {
            const int h = warp >> 2;
            float a0 = 0.f, a1 = 0.f, a2 = 0.f, a3 = 0.f, ps = 0.f;
            const uint2* vt = g_V4 + ((size_t)b * 32 + warp) * NPAD;
            const float* pp = smp + h * NPAD;
            #pragma unroll 4
            for (int n = lane; n < M_pad; n += 32) {
                const uint2 r = vt[n];
                const float p = pp[n];
                const float2 v0 = __bfloat1622float2(*(const __nv_bfloat162*)&r.x);
                const float2 v1 = __bfloat1622float2(*(const __nv_bfloat162*)&r.y);
                ps += p;
                a0 += p * v0.x; a1 += p * v0.y; a2 += p * v1.x; a3 += p * v1.y;
            }
            #pragma unroll
            for (int o = 16; o > 0; o >>= 1) {
                a0 += __shfl_xor_sync(~0u, a0, o);
                a1 += __shfl_xor_sync(~0u, a1, o);
                a2 += __shfl_xor_sync(~0u, a2, o);
                a3 += __shfl_xor_sync(~0u, a3, o);
                ps += __shfl_xor_sync(~0u, ps, o);
            }
            if (lane == 0) {
                const float inv = 1.0f / ps;
                sm_ctx[warp * 4 + 0] = a0 * inv;
                sm_ctx[warp * 4 + 1] = a1 * inv;
                sm_ctx[warp * 4 + 2] = a2 * inv;
                sm_ctx[warp * 4 + 3] = a3 * inv;
            }
        }
        __syncthreads();   // S3

        // ---- F: logits = ctx.G + blk; fused argmax + sum exp ----
        {
            float mv = NEGV, s = 0.f;
            int   mi = t;
            if (t < M_pad) {
                float a = sm_blk[t];
                #pragma unroll
                for (int c4 = 0; c4 < 32; ++c4) {
                    const uint2 r = gq[(size_t)c4 * NPAD];
                    const float2 l0 = __bfloat1622float2(*(const __nv_bfloat162*)&r.x);
                    const float2 l1 = __bfloat1622float2(*(const __nv_bfloat162*)&r.y);
                    const float4 xv = *(const float4*)&sm_ctx[4 * c4];
                    a += xv.x * l0.x + xv.y * l0.y + xv.z * l1.x + xv.w * l1.y;
                }
                if (!msk) {
                    mv = a;
                    s  = __expf(tanh_fast(a * SCALE) * 10.0f);
                }
                #pragma unroll
                for (int o = 16; o > 0; o >>= 1) {
                    const float ov = __shfl_xor_sync(~0u, mv, o);
                    const int   oi = __shfl_xor_sync(~0u, mi, o);
                    s += __shfl_xor_sync(~0u, s, o);
                    if (ov > mv || (ov == mv && oi < mi)) { mv = ov; mi = oi; }
                }
            }
            if (lane == 0) {
                sm_wred[warp * 9 + 0] = mv;
                sm_wred[warp * 9 + 1] = s;
                sm_iwred[warp] = mi;
            }
        }
        __syncthreads();   // S4

        // ---- final reduce, redundant in every warp ----
        {
            float mv = sm_wred[lane * 9 + 0];
            float s  = sm_wred[lane * 9 + 1];
            int   mi = sm_iwred[lane];
            #pragma unroll
            for (int o = 16; o > 0; o >>= 1) {
                const float ov = __shfl_xor_sync(~0u, mv, o);
                const int   oi = __shfl_xor_sync(~0u, mi, o);
                s += __shfl_xor_sync(~0u, s, o);
                if (ov > mv || (ov == mv && oi < mi)) { mv = ov; mi = oi; }
            }
            if (t == 0) {
                total += tanhf(mv * SCALE) * 10.0f - logf(s);  // precise winner
                sm_mask[mi] = 1;
            }
            cur = sm_idx[mi];
        }

        // ---- periodic stable compaction of active tokens ----
        if (((step + 1) & 63) == 0) {
            __syncthreads();                 // CS1
            if (warp == 0) {
                int cnt = 0;
                if (lane < nch) {
                    const unsigned char* mp = sm_mask + lane * 32;
                    #pragma unroll
                    for (int j = 0; j < 32; ++j) cnt += (mp[j] == 0);
                }
                int inc = cnt;
                #pragma unroll
                for (int o = 1; o < 32; o <<= 1) {
                    const int v = __shfl_up_sync(~0u, inc, o);
                    if (lane >= o) inc += v;
                }
                if (lane < nch) sm_cbase[lane] = inc - cnt;
                if (lane == nch - 1) sm_newM = inc;
            }
            __syncthreads();                 // CS2
            {
                uint2* rows[3] = {
                    g_K4 + ((size_t)b * 32 + warp) * NPAD,
                    g_V4 + ((size_t)b * 32 + warp) * NPAD,
                    g_G4 + ((size_t)b * 32 + warp) * NPAD };
                #pragma unroll
                for (int a = 0; a < 3; ++a) {
                    uint2* row = rows[a];
                    for (int c = 0; c < nch; ++c) {
                        const int n = c * 32 + lane;
                        const uint2 v = row[n];
                        const bool keep = (sm_mask[n] == 0);
                        const unsigned bal = __ballot_sync(~0u, keep);
                        if (keep)
                            row[sm_cbase[c] + __popc(bal & ((1u << lane) - 1))] = v;
                    }
                }
                if (warp == 0) {
                    for (int c = 0; c < nch; ++c) {
                        const int n = c * 32 + lane;
                        const float v = sm_blk[n];
                        const bool keep = (sm_mask[n] == 0);
                        const unsigned bal = __ballot_sync(~0u, keep);
                        if (keep)
                            sm_blk[sm_cbase[c] + __popc(bal & ((1u << lane) - 1))] = v;
                    }
                }
                if (warp == 1) {
                    for (int c = 0; c < nch; ++c) {
                        const int n = c * 32 + lane;
                        const int v = sm_idx[n];
                        const bool keep = (sm_mask[n] == 0);
                        const unsigned bal = __ballot_sync(~0u, keep);
                        if (keep)
                            sm_idx[sm_cbase[c] + __popc(bal & ((1u << lane) - 1))] = v;
                    }
                }
            }
            __syncthreads();                 // CS3
            const int M = sm_newM;
            M_pad = (M + 31) & ~31;          // pad to 32 (was 128)
            nch   = M_pad >> 5;
            sm_mask[t] = (t >= M) ? 1 : 0;
        }
    }

    if (t == 0) out[b] = total;
}

// ---------------------------------------------------------------------------
extern "C" void kernel_launch(void* const* d_in, const int* in_sizes, int n_in,
                              void* d_out, int out_size) {
    const float* node  = (const float*)d_in[0];
    const float* graph = (const float*)d_in[1];
    const float* Wqkv  = (const float*)d_in[2];
    const float* bqkv  = (const float*)d_in[3];
    const float* Wfix  = (const float*)d_in[4];
    const float* bfix  = (const float*)d_in[5];
    const float* Wstep = (const float*)d_in[6];
    const float* bstep = (const float*)d_in[7];
    const float* Wmlp  = (const float*)d_in[8];
    const float* bmlp  = (const float*)d_in[9];
    float* out = (float*)d_out;

    dim3 blk2(16, 16);
    qkv_gemm<<<dim3(6, 16, BB), blk2>>>(node, Wqkv, bqkv);
    sk_gemm <<<dim3(2, 16, BB), blk2>>>(node, Wstep);
    g_gemm  <<<dim3(2, 16, BB), blk2>>>(Wmlp);
    blk_kernel <<<BB, NPAD>>>(bmlp);
    qbase_kernel<<<BB, EE>>>(graph, node, Wfix, bfix, Wstep, bstep);
    decode_loop<<<BB, 1024>>>(out);
}

// round 9
// speedup vs baseline: 1.2731x; 1.0429x over previous
#include <cuda_runtime.h>
#include <cuda_bf16.h>
#include <math.h>

#define BB   128
#define NTOK 1000
#define NPAD 1024
#define EE   128
#define HH   8
#define NEGV (-1000000000.0f)
#define SCALE 0.25f

// K, G oct-interleaved:  (b,e,n) -> bf16 ((b*16 + (e>>3))*NPAD + n)*8 + (e&7)
// V quad-interleaved:    (b,e,n) -> bf16 ((b*32 + (e>>2))*NPAD + n)*4 + (e&3)
__device__ uint4 g_K8[BB * 16 * NPAD];
__device__ uint4 g_G8[BB * 16 * NPAD];
__device__ uint2 g_V4[BB * 32 * NPAD];
__device__ __nv_bfloat16 g_LKp[BB * EE * NPAD];
__device__ float g_SK   [(size_t)BB * NTOK * EE];   // node @ Wstep[128:]
__device__ float g_qbase[BB * EE];
__device__ float g_blk  [BB * NPAD];                // bmlp . LK[:,n]

// ---------------------------------------------------------------------------
// Precompute 1: qkv = node @ Wqkv + bqkv -> K8 / V4 / LKp
// ---------------------------------------------------------------------------
__global__ void qkv_gemm(const float* __restrict__ node,
                         const float* __restrict__ W,
                         const float* __restrict__ bias) {
    __shared__ float As[16][64];
    __shared__ float Bs[16][64];
    const int b  = blockIdx.z;
    const int n0 = blockIdx.y * 64;
    const int e0 = blockIdx.x * 64;
    const int tx = threadIdx.x, ty = threadIdx.y;
    const int t  = ty * 16 + tx;
    const int an = t >> 2, ak = (t & 3) * 4;
    const int bk = t >> 4, be = (t & 15) * 4;

    float acc[4][4] = {};
    for (int k0 = 0; k0 < 128; k0 += 16) {
        float4 av;
        const int n = n0 + an;
        if (n < NTOK) av = *(const float4*)&node[((size_t)b * NTOK + n) * EE + k0 + ak];
        else          av = make_float4(0.f, 0.f, 0.f, 0.f);
        As[ak + 0][an] = av.x; As[ak + 1][an] = av.y;
        As[ak + 2][an] = av.z; As[ak + 3][an] = av.w;
        *(float4*)&Bs[bk][be] = *(const float4*)&W[(size_t)(k0 + bk) * 384 + e0 + be];
        __syncthreads();
        #pragma unroll
        for (int kk = 0; kk < 16; ++kk) {
            float ar[4], br[4];
            #pragma unroll
            for (int i = 0; i < 4; ++i) ar[i] = As[kk][ty * 4 + i];
            #pragma unroll
            for (int j = 0; j < 4; ++j) br[j] = Bs[kk][tx * 4 + j];
            #pragma unroll
            for (int i = 0; i < 4; ++i)
                #pragma unroll
                for (int j = 0; j < 4; ++j) acc[i][j] += ar[i] * br[j];
        }
        __syncthreads();
    }

    __nv_bfloat16* K = (__nv_bfloat16*)g_K8;
    __nv_bfloat16* V = (__nv_bfloat16*)g_V4;
    #pragma unroll
    for (int i = 0; i < 4; ++i) {
        const int n = n0 + ty * 4 + i;
        if (n >= NTOK) continue;
        #pragma unroll
        for (int j = 0; j < 4; ++j) {
            const int e3 = e0 + tx * 4 + j;
            const __nv_bfloat16 bv = __float2bfloat16(acc[i][j] + bias[e3]);
            if (e3 < 128) {
                const int e = e3;
                K[((size_t)(b * 16 + (e >> 3)) * NPAD + n) * 8 + (e & 7)] = bv;
            } else if (e3 < 256) {
                const int e = e3 - 128;
                V[((size_t)(b * 32 + (e >> 2)) * NPAD + n) * 4 + (e & 3)] = bv;
            } else {
                const int e = e3 - 256;
                g_LKp[(size_t)(b * EE + e) * NPAD + n] = bv;
            }
        }
    }
}

// ---------------------------------------------------------------------------
// Precompute 2: SK[b][n][e] = node[b,n] @ Wstep[128:256]  (fp32)
// ---------------------------------------------------------------------------
__global__ void sk_gemm(const float* __restrict__ node,
                        const float* __restrict__ Wstep) {
    __shared__ float As[16][64];
    __shared__ float Bs[16][64];
    const float* W2 = Wstep + 128 * EE;
    const int b  = blockIdx.z;
    const int n0 = blockIdx.y * 64;
    const int e0 = blockIdx.x * 64;
    const int tx = threadIdx.x, ty = threadIdx.y;
    const int t  = ty * 16 + tx;
    const int an = t >> 2, ak = (t & 3) * 4;
    const int bk = t >> 4, be = (t & 15) * 4;

    float acc[4][4] = {};
    for (int k0 = 0; k0 < 128; k0 += 16) {
        float4 av;
        const int n = n0 + an;
        if (n < NTOK) av = *(const float4*)&node[((size_t)b * NTOK + n) * EE + k0 + ak];
        else          av = make_float4(0.f, 0.f, 0.f, 0.f);
        As[ak + 0][an] = av.x; As[ak + 1][an] = av.y;
        As[ak + 2][an] = av.z; As[ak + 3][an] = av.w;
        *(float4*)&Bs[bk][be] = *(const float4*)&W2[(size_t)(k0 + bk) * EE + e0 + be];
        __syncthreads();
        #pragma unroll
        for (int kk = 0; kk < 16; ++kk) {
            float ar[4], br[4];
            #pragma unroll
            for (int i = 0; i < 4; ++i) ar[i] = As[kk][ty * 4 + i];
            #pragma unroll
            for (int j = 0; j < 4; ++j) br[j] = Bs[kk][tx * 4 + j];
            #pragma unroll
            for (int i = 0; i < 4; ++i)
                #pragma unroll
                for (int j = 0; j < 4; ++j) acc[i][j] += ar[i] * br[j];
        }
        __syncthreads();
    }
    #pragma unroll
    for (int i = 0; i < 4; ++i) {
        const int n = n0 + ty * 4 + i;
        if (n >= NTOK) continue;
        #pragma unroll
        for (int j = 0; j < 4; ++j)
            g_SK[((size_t)b * NTOK + n) * EE + e0 + tx * 4 + j] = acc[i][j];
    }
}

// ---------------------------------------------------------------------------
// Precompute 3: G[b][c][n] = Wmlp[c][:] . LK[b][:][n]  -> oct-interleaved bf16
// ---------------------------------------------------------------------------
__global__ void g_gemm(const float* __restrict__ Wmlp) {
    __shared__ float As[16][64];   // [e][c]
    __shared__ float Bs[16][64];   // [e][n]
    const int b  = blockIdx.z;
    const int n0 = blockIdx.y * 64;
    const int c0 = blockIdx.x * 64;
    const int tx = threadIdx.x, ty = threadIdx.y;
    const int t  = ty * 16 + tx;
    const int ac = t >> 2, ae = (t & 3) * 4;
    const int bk = t >> 4, bn = (t & 15) * 4;

    float acc[4][4] = {};
    for (int k0 = 0; k0 < 128; k0 += 16) {
        const float4 av = *(const float4*)&Wmlp[(size_t)(c0 + ac) * EE + k0 + ae];
        As[ae + 0][ac] = av.x; As[ae + 1][ac] = av.y;
        As[ae + 2][ac] = av.z; As[ae + 3][ac] = av.w;
        const uint2 r = *(const uint2*)&g_LKp[(size_t)(b * EE + k0 + bk) * NPAD + n0 + bn];
        const float2 v0 = __bfloat1622float2(*(const __nv_bfloat162*)&r.x);
        const float2 v1 = __bfloat1622float2(*(const __nv_bfloat162*)&r.y);
        Bs[bk][bn + 0] = v0.x; Bs[bk][bn + 1] = v0.y;
        Bs[bk][bn + 2] = v1.x; Bs[bk][bn + 3] = v1.y;
        __syncthreads();
        #pragma unroll
        for (int kk = 0; kk < 16; ++kk) {
            float ar[4], br[4];
            #pragma unroll
            for (int i = 0; i < 4; ++i) ar[i] = As[kk][ty * 4 + i];
            #pragma unroll
            for (int j = 0; j < 4; ++j) br[j] = Bs[kk][tx * 4 + j];
            #pragma unroll
            for (int i = 0; i < 4; ++i)
                #pragma unroll
                for (int j = 0; j < 4; ++j) acc[i][j] += ar[i] * br[j];
        }
        __syncthreads();
    }
    __nv_bfloat16* G = (__nv_bfloat16*)g_G8;
    #pragma unroll
    for (int i = 0; i < 4; ++i) {
        const int c = c0 + ty * 4 + i;
        #pragma unroll
        for (int j = 0; j < 4; ++j) {
            const int n = n0 + tx * 4 + j;
            G[((size_t)(b * 16 + (c >> 3)) * NPAD + n) * 8 + (c & 7)] =
                __float2bfloat16(acc[i][j]);
        }
    }
}

// ---------------------------------------------------------------------------
// Precompute 4: blk[b][n] = bmlp . LK[b][:][n]
// ---------------------------------------------------------------------------
__global__ void blk_kernel(const float* __restrict__ bmlp) {
    const int b = blockIdx.x, n = threadIdx.x;
    __shared__ float bm[EE];
    if (n < EE) bm[n] = bmlp[n];
    __syncthreads();
    float a = 0.f;
    #pragma unroll 8
    for (int e = 0; e < EE; ++e)
        a += bm[e] * __bfloat162float(g_LKp[(size_t)(b * EE + e) * NPAD + n]);
    g_blk[b * NPAD + n] = a;
}

// ---------------------------------------------------------------------------
// Precompute 5: qbase = graph@Wfix + bfix + bstep + first@Wstep[:128]
// ---------------------------------------------------------------------------
__global__ void qbase_kernel(const float* __restrict__ g,
                             const float* __restrict__ node,
                             const float* __restrict__ Wfix,
                             const float* __restrict__ bfix,
                             const float* __restrict__ Wstep,
                             const float* __restrict__ bstep) {
    const int b = blockIdx.x, e = threadIdx.x;
    __shared__ float gs[EE], fs[EE];
    gs[e] = g[b * EE + e];
    fs[e] = node[(size_t)b * NTOK * EE + e];
    __syncthreads();
    float a = bfix[e] + bstep[e];
    #pragma unroll 4
    for (int k = 0; k < EE; ++k) {
        a += gs[k] * Wfix[(size_t)k * EE + e];
        a += fs[k] * Wstep[(size_t)k * EE + e];
    }
    g_qbase[b * EE + e] = a;
}

__device__ __forceinline__ float tanh_fast(float x) {
    float r;
    asm("tanh.approx.f32 %0, %1;" : "=f"(r) : "f"(x));
    return r;
}

// dot of 8 bf16 (uint4) with 8 fp32 from aligned smem
__device__ __forceinline__ float dot8(const uint4 r, const float* __restrict__ q) {
    const float2 f0 = __bfloat1622float2(*(const __nv_bfloat162*)&r.x);
    const float2 f1 = __bfloat1622float2(*(const __nv_bfloat162*)&r.y);
    const float2 f2 = __bfloat1622float2(*(const __nv_bfloat162*)&r.z);
    const float2 f3 = __bfloat1622float2(*(const __nv_bfloat162*)&r.w);
    const float4 q0 = *(const float4*)q;
    const float4 q1 = *(const float4*)(q + 4);
    return q0.x * f0.x + q0.y * f0.y + q0.z * f1.x + q0.w * f1.y
         + q1.x * f2.x + q1.y * f2.y + q1.z * f3.x + q1.w * f3.y;
}

// ---------------------------------------------------------------------------
// Persistent decode loop with periodic active-token compaction.
// ---------------------------------------------------------------------------
__global__ void __launch_bounds__(1024, 1)
decode_loop(float* __restrict__ out) {
    const int b    = blockIdx.x;
    const int t    = threadIdx.x;
    const int warp = t >> 5, lane = t & 31;

    __shared__ __align__(16) float smp[HH * NPAD];   // 32 KB
    __shared__ float sm_blk[NPAD];                   // 4 KB
    __shared__ int   sm_idx[NPAD];                   // 4 KB
    __shared__ float sm_wred[32 * 9];
    __shared__ int   sm_iwred[32];
    __shared__ __align__(16) float sm_q[EE];
    __shared__ __align__(16) float sm_ctx[EE];
    __shared__ float sm_qbase[EE];
    __shared__ unsigned char sm_mask[NPAD];
    __shared__ int   sm_cbase[32];
    __shared__ int   sm_newM;

    if (t < EE) sm_qbase[t] = g_qbase[b * EE + t];
    sm_blk[t]  = g_blk[b * NPAD + t];
    sm_idx[t]  = t;
    sm_mask[t] = (t == 0 || t >= NTOK) ? 1 : 0;
    __syncthreads();

    const uint4* kq = g_K8 + (size_t)b * 16 * NPAD + t;
    const uint4* gq = g_G8 + (size_t)b * 16 * NPAD + t;
    int   cur   = 0;
    float total = 0.f;
    int   M_pad = NPAD;    // active slots (rounded to 32)
    int   nch   = NPAD / 32;

    #pragma unroll 1
    for (int step = 0; step < NTOK - 1; ++step) {
        // ---- q row: qbase + SK[cur] ----
        if (t < EE)
            sm_q[t] = sm_qbase[t] + g_SK[((size_t)b * NTOK + cur) * EE + t];
        __syncthreads();   // S1 (publishes q + mask/compaction from prev iter)

        // ---- C: scores, p = exp (no max-shift); no reduction here ----
        const bool msk = sm_mask[t];
        if (t < M_pad) {
            #pragma unroll
            for (int h = 0; h < HH; ++h) {
                const float a = dot8(kq[(size_t)(2 * h)     * NPAD], &sm_q[h * 16])
                              + dot8(kq[(size_t)(2 * h + 1) * NPAD], &sm_q[h * 16 + 8]);
                smp[h * NPAD + t] = msk ? 0.f : __expf(a * SCALE);
            }
        }
        __syncthreads();   // S2

        // ---- D: ctx; warp w owns quad w (e = 4w..4w+3), h = w>>2;
        //      per-head softmax sum folded into the n-loop ----
        {
            const int h = warp >> 2;
            float a0 = 0.f, a1 = 0.f, a2 = 0.f, a3 = 0.f, ps = 0.f;
            const uint2* vt = g_V4 + ((size_t)b * 32 + warp) * NPAD;
            const float* pp = smp + h * NPAD;
            #pragma unroll 4
            for (int n = lane; n < M_pad; n += 32) {
                const uint2 r = vt[n];
                const float p = pp[n];
                const float2 v0 = __bfloat1622float2(*(const __nv_bfloat162*)&r.x);
                const float2 v1 = __bfloat1622float2(*(const __nv_bfloat162*)&r.y);
                ps += p;
                a0 += p * v0.x; a1 += p * v0.y; a2 += p * v1.x; a3 += p * v1.y;
            }
            #pragma unroll
            for (int o = 16; o > 0; o >>= 1) {
                a0 += __shfl_xor_sync(~0u, a0, o);
                a1 += __shfl_xor_sync(~0u, a1, o);
                a2 += __shfl_xor_sync(~0u, a2, o);
                a3 += __shfl_xor_sync(~0u, a3, o);
                ps += __shfl_xor_sync(~0u, ps, o);
            }
            if (lane == 0) {
                const float inv = 1.0f / ps;
                sm_ctx[warp * 4 + 0] = a0 * inv;
                sm_ctx[warp * 4 + 1] = a1 * inv;
                sm_ctx[warp * 4 + 2] = a2 * inv;
                sm_ctx[warp * 4 + 3] = a3 * inv;
            }
        }
        __syncthreads();   // S3

        // ---- F: logits = ctx.G + blk; fused argmax + sum exp ----
        {
            float mv = NEGV, s = 0.f;
            int   mi = t;
            if (t < M_pad) {
                float a = sm_blk[t];
                #pragma unroll
                for (int o8 = 0; o8 < 16; ++o8)
                    a += dot8(gq[(size_t)o8 * NPAD], &sm_ctx[o8 * 8]);
                if (!msk) {
                    mv = a;
                    s  = __expf(tanh_fast(a * SCALE) * 10.0f);
                }
                #pragma unroll
                for (int o = 16; o > 0; o >>= 1) {
                    const float ov = __shfl_xor_sync(~0u, mv, o);
                    const int   oi = __shfl_xor_sync(~0u, mi, o);
                    s += __shfl_xor_sync(~0u, s, o);
                    if (ov > mv || (ov == mv && oi < mi)) { mv = ov; mi = oi; }
                }
            }
            if (lane == 0) {
                sm_wred[warp * 9 + 0] = mv;
                sm_wred[warp * 9 + 1] = s;
                sm_iwred[warp] = mi;
            }
        }
        __syncthreads();   // S4

        // ---- final reduce, redundant in every warp ----
        {
            float mv = sm_wred[lane * 9 + 0];
            float s  = sm_wred[lane * 9 + 1];
            int   mi = sm_iwred[lane];
            #pragma unroll
            for (int o = 16; o > 0; o >>= 1) {
                const float ov = __shfl_xor_sync(~0u, mv, o);
                const int   oi = __shfl_xor_sync(~0u, mi, o);
                s += __shfl_xor_sync(~0u, s, o);
                if (ov > mv || (ov == mv && oi < mi)) { mv = ov; mi = oi; }
            }
            if (t == 0) {
                total += tanhf(mv * SCALE) * 10.0f - logf(s);  // precise winner
                sm_mask[mi] = 1;
            }
            cur = sm_idx[mi];
        }

        // ---- periodic stable compaction of active tokens ----
        if (((step + 1) & 63) == 0) {
            __syncthreads();                 // CS1
            if (warp == 0) {
                int cnt = 0;
                if (lane < nch) {
                    const unsigned char* mp = sm_mask + lane * 32;
                    #pragma unroll
                    for (int j = 0; j < 32; ++j) cnt += (mp[j] == 0);
                }
                int inc = cnt;
                #pragma unroll
                for (int o = 1; o < 32; o <<= 1) {
                    const int v = __shfl_up_sync(~0u, inc, o);
                    if (lane >= o) inc += v;
                }
                if (lane < nch) sm_cbase[lane] = inc - cnt;
                if (lane == nch - 1) sm_newM = inc;
            }
            __syncthreads();                 // CS2
            {
                // rows 0..15: K8 (uint4), 16..31: G8 (uint4), 32..63: V4 (uint2)
                for (int rr = warp; rr < 64; rr += 32) {
                    if (rr < 32) {
                        uint4* row = (rr < 16 ? g_K8 + ((size_t)b * 16 + rr) * NPAD
                                              : g_G8 + ((size_t)b * 16 + rr - 16) * NPAD);
                        for (int c = 0; c < nch; ++c) {
                            const int n = c * 32 + lane;
                            const uint4 v = row[n];
                            const bool keep = (sm_mask[n] == 0);
                            const unsigned bal = __ballot_sync(~0u, keep);
                            if (keep)
                                row[sm_cbase[c] + __popc(bal & ((1u << lane) - 1))] = v;
                        }
                    } else {
                        uint2* row = g_V4 + ((size_t)b * 32 + rr - 32) * NPAD;
                        for (int c = 0; c < nch; ++c) {
                            const int n = c * 32 + lane;
                            const uint2 v = row[n];
                            const bool keep = (sm_mask[n] == 0);
                            const unsigned bal = __ballot_sync(~0u, keep);
                            if (keep)
                                row[sm_cbase[c] + __popc(bal & ((1u << lane) - 1))] = v;
                        }
                    }
                }
                if (warp == 0) {
                    for (int c = 0; c < nch; ++c) {
                        const int n = c * 32 + lane;
                        const float v = sm_blk[n];
                        const bool keep = (sm_mask[n] == 0);
                        const unsigned bal = __ballot_sync(~0u, keep);
                        if (keep)
                            sm_blk[sm_cbase[c] + __popc(bal & ((1u << lane) - 1))] = v;
                    }
                }
                if (warp == 1) {
                    for (int c = 0; c < nch; ++c) {
                        const int n = c * 32 + lane;
                        const int v = sm_idx[n];
                        const bool keep = (sm_mask[n] == 0);
                        const unsigned bal = __ballot_sync(~0u, keep);
                        if (keep)
                            sm_idx[sm_cbase[c] + __popc(bal & ((1u << lane) - 1))] = v;
                    }
                }
            }
            __syncthreads();                 // CS3
            const int M = sm_newM;
            M_pad = (M + 31) & ~31;
            nch   = M_pad >> 5;
            sm_mask[t] = (t >= M) ? 1 : 0;
        }
    }

    if (t == 0) out[b] = total;
}

// ---------------------------------------------------------------------------
extern "C" void kernel_launch(void* const* d_in, const int* in_sizes, int n_in,
                              void* d_out, int out_size) {
    const float* node  = (const float*)d_in[0];
    const float* graph = (const float*)d_in[1];
    const float* Wqkv  = (const float*)d_in[2];
    const float* bqkv  = (const float*)d_in[3];
    const float* Wfix  = (const float*)d_in[4];
    const float* bfix  = (const float*)d_in[5];
    const float* Wstep = (const float*)d_in[6];
    const float* bstep = (const float*)d_in[7];
    const float* Wmlp  = (const float*)d_in[8];
    const float* bmlp  = (const float*)d_in[9];
    float* out = (float*)d_out;

    dim3 blk2(16, 16);
    qkv_gemm<<<dim3(6, 16, BB), blk2>>>(node, Wqkv, bqkv);
    sk_gemm <<<dim3(2, 16, BB), blk2>>>(node, Wstep);
    g_gemm  <<<dim3(2, 16, BB), blk2>>>(Wmlp);
    blk_kernel <<<BB, NPAD>>>(bmlp);
    qbase_kernel<<<BB, EE>>>(graph, node, Wfix, bfix, Wstep, bstep);
    decode_loop<<<BB, 1024>>>(out);
}

// round 10
// speedup vs baseline: 1.6844x; 1.3231x over previous
#include <cuda_runtime.h>
#include <cuda_bf16.h>
#include <cuda_fp16.h>
#include <cuda_fp8.h>
#include <math.h>

#define BB   128
#define NTOK 1000
#define NPAD 1024
#define EE   128
#define HH   8
#define NEGV (-1000000000.0f)
#define SCALE 0.25f
#define FP8S 256.0f            // storage scale for e4m3
#define SC_C (0.25f / 256.0f)  // score scale incl. fp8 unscale

// K, G: 16-feature interleave (one head / one c-group per uint4 of e4m3):
//   (b,e,n) -> fp8 byte ((b*8 + (e>>4))*NPAD + n)*16 + (e&15)
// V: 4-feature quads of e4m3: (b,e,n) -> fp8 byte ((b*32 + (e>>2))*NPAD + n)*4 + (e&3)
__device__ uint4    g_K16[BB * 8 * NPAD];
__device__ uint4    g_G16[BB * 8 * NPAD];
__device__ unsigned g_V4u[BB * 32 * NPAD];
__device__ __nv_bfloat16 g_LKp[BB * EE * NPAD];
__device__ float g_SK   [(size_t)BB * NTOK * EE];   // node @ Wstep[128:]
__device__ float g_qbase[BB * EE];
__device__ float g_blk  [BB * NPAD];                // bmlp . LK[:,n]

static __device__ __forceinline__ unsigned char to_fp8(float v) {
    return (unsigned char)__nv_cvt_float_to_fp8(v * FP8S, __NV_SATFINITE, __NV_E4M3);
}

// ---------------------------------------------------------------------------
// Precompute 1: qkv = node @ Wqkv + bqkv -> K16(fp8) / V4u(fp8) / LKp(bf16)
// ---------------------------------------------------------------------------
__global__ void qkv_gemm(const float* __restrict__ node,
                         const float* __restrict__ W,
                         const float* __restrict__ bias) {
    __shared__ float As[16][64];
    __shared__ float Bs[16][64];
    const int b  = blockIdx.z;
    const int n0 = blockIdx.y * 64;
    const int e0 = blockIdx.x * 64;
    const int tx = threadIdx.x, ty = threadIdx.y;
    const int t  = ty * 16 + tx;
    const int an = t >> 2, ak = (t & 3) * 4;
    const int bk = t >> 4, be = (t & 15) * 4;

    float acc[4][4] = {};
    for (int k0 = 0; k0 < 128; k0 += 16) {
        float4 av;
        const int n = n0 + an;
        if (n < NTOK) av = *(const float4*)&node[((size_t)b * NTOK + n) * EE + k0 + ak];
        else          av = make_float4(0.f, 0.f, 0.f, 0.f);
        As[ak + 0][an] = av.x; As[ak + 1][an] = av.y;
        As[ak + 2][an] = av.z; As[ak + 3][an] = av.w;
        *(float4*)&Bs[bk][be] = *(const float4*)&W[(size_t)(k0 + bk) * 384 + e0 + be];
        __syncthreads();
        #pragma unroll
        for (int kk = 0; kk < 16; ++kk) {
            float ar[4], br[4];
            #pragma unroll
            for (int i = 0; i < 4; ++i) ar[i] = As[kk][ty * 4 + i];
            #pragma unroll
            for (int j = 0; j < 4; ++j) br[j] = Bs[kk][tx * 4 + j];
            #pragma unroll
            for (int i = 0; i < 4; ++i)
                #pragma unroll
                for (int j = 0; j < 4; ++j) acc[i][j] += ar[i] * br[j];
        }
        __syncthreads();
    }

    unsigned char* K = (unsigned char*)g_K16;
    unsigned char* V = (unsigned char*)g_V4u;
    #pragma unroll
    for (int i = 0; i < 4; ++i) {
        const int n = n0 + ty * 4 + i;
        if (n >= NTOK) continue;
        #pragma unroll
        for (int j = 0; j < 4; ++j) {
            const int e3 = e0 + tx * 4 + j;
            const float v = acc[i][j] + bias[e3];
            if (e3 < 128) {
                const int e = e3;
                K[((size_t)(b * 8 + (e >> 4)) * NPAD + n) * 16 + (e & 15)] = to_fp8(v);
            } else if (e3 < 256) {
                const int e = e3 - 128;
                V[((size_t)(b * 32 + (e >> 2)) * NPAD + n) * 4 + (e & 3)] = to_fp8(v);
            } else {
                const int e = e3 - 256;
                g_LKp[(size_t)(b * EE + e) * NPAD + n] = __float2bfloat16(v);
            }
        }
    }
}

// ---------------------------------------------------------------------------
// Precompute 2: SK[b][n][e] = node[b,n] @ Wstep[128:256]  (fp32)
// ---------------------------------------------------------------------------
__global__ void sk_gemm(const float* __restrict__ node,
                        const float* __restrict__ Wstep) {
    __shared__ float As[16][64];
    __shared__ float Bs[16][64];
    const float* W2 = Wstep + 128 * EE;
    const int b  = blockIdx.z;
    const int n0 = blockIdx.y * 64;
    const int e0 = blockIdx.x * 64;
    const int tx = threadIdx.x, ty = threadIdx.y;
    const int t  = ty * 16 + tx;
    const int an = t >> 2, ak = (t & 3) * 4;
    const int bk = t >> 4, be = (t & 15) * 4;

    float acc[4][4] = {};
    for (int k0 = 0; k0 < 128; k0 += 16) {
        float4 av;
        const int n = n0 + an;
        if (n < NTOK) av = *(const float4*)&node[((size_t)b * NTOK + n) * EE + k0 + ak];
        else          av = make_float4(0.f, 0.f, 0.f, 0.f);
        As[ak + 0][an] = av.x; As[ak + 1][an] = av.y;
        As[ak + 2][an] = av.z; As[ak + 3][an] = av.w;
        *(float4*)&Bs[bk][be] = *(const float4*)&W2[(size_t)(k0 + bk) * EE + e0 + be];
        __syncthreads();
        #pragma unroll
        for (int kk = 0; kk < 16; ++kk) {
            float ar[4], br[4];
            #pragma unroll
            for (int i = 0; i < 4; ++i) ar[i] = As[kk][ty * 4 + i];
            #pragma unroll
            for (int j = 0; j < 4; ++j) br[j] = Bs[kk][tx * 4 + j];
            #pragma unroll
            for (int i = 0; i < 4; ++i)
                #pragma unroll
                for (int j = 0; j < 4; ++j) acc[i][j] += ar[i] * br[j];
        }
        __syncthreads();
    }
    #pragma unroll
    for (int i = 0; i < 4; ++i) {
        const int n = n0 + ty * 4 + i;
        if (n >= NTOK) continue;
        #pragma unroll
        for (int j = 0; j < 4; ++j)
            g_SK[((size_t)b * NTOK + n) * EE + e0 + tx * 4 + j] = acc[i][j];
    }
}

// ---------------------------------------------------------------------------
// Precompute 3: G[b][c][n] = Wmlp[c][:] . LK[b][:][n]  -> 16-interleaved fp8
// ---------------------------------------------------------------------------
__global__ void g_gemm(const float* __restrict__ Wmlp) {
    __shared__ float As[16][64];   // [e][c]
    __shared__ float Bs[16][64];   // [e][n]
    const int b  = blockIdx.z;
    const int n0 = blockIdx.y * 64;
    const int c0 = blockIdx.x * 64;
    const int tx = threadIdx.x, ty = threadIdx.y;
    const int t  = ty * 16 + tx;
    const int ac = t >> 2, ae = (t & 3) * 4;
    const int bk = t >> 4, bn = (t & 15) * 4;

    float acc[4][4] = {};
    for (int k0 = 0; k0 < 128; k0 += 16) {
        const float4 av = *(const float4*)&Wmlp[(size_t)(c0 + ac) * EE + k0 + ae];
        As[ae + 0][ac] = av.x; As[ae + 1][ac] = av.y;
        As[ae + 2][ac] = av.z; As[ae + 3][ac] = av.w;
        const uint2 r = *(const uint2*)&g_LKp[(size_t)(b * EE + k0 + bk) * NPAD + n0 + bn];
        const float2 v0 = __bfloat1622float2(*(const __nv_bfloat162*)&r.x);
        const float2 v1 = __bfloat1622float2(*(const __nv_bfloat162*)&r.y);
        Bs[bk][bn + 0] = v0.x; Bs[bk][bn + 1] = v0.y;
        Bs[bk][bn + 2] = v1.x; Bs[bk][bn + 3] = v1.y;
        __syncthreads();
        #pragma unroll
        for (int kk = 0; kk < 16; ++kk) {
            float ar[4], br[4];
            #pragma unroll
            for (int i = 0; i < 4; ++i) ar[i] = As[kk][ty * 4 + i];
            #pragma unroll
            for (int j = 0; j < 4; ++j) br[j] = Bs[kk][tx * 4 + j];
            #pragma unroll
            for (int i = 0; i < 4; ++i)
                #pragma unroll
                for (int j = 0; j < 4; ++j) acc[i][j] += ar[i] * br[j];
        }
        __syncthreads();
    }
    unsigned char* G = (unsigned char*)g_G16;
    #pragma unroll
    for (int i = 0; i < 4; ++i) {
        const int c = c0 + ty * 4 + i;
        #pragma unroll
        for (int j = 0; j < 4; ++j) {
            const int n = n0 + tx * 4 + j;
            G[((size_t)(b * 8 + (c >> 4)) * NPAD + n) * 16 + (c & 15)] = to_fp8(acc[i][j]);
        }
    }
}

// ---------------------------------------------------------------------------
// Precompute 4: blk[b][n] = bmlp . LK[b][:][n]
// ---------------------------------------------------------------------------
__global__ void blk_kernel(const float* __restrict__ bmlp) {
    const int b = blockIdx.x, n = threadIdx.x;
    __shared__ float bm[EE];
    if (n < EE) bm[n] = bmlp[n];
    __syncthreads();
    float a = 0.f;
    #pragma unroll 8
    for (int e = 0; e < EE; ++e)
        a += bm[e] * __bfloat162float(g_LKp[(size_t)(b * EE + e) * NPAD + n]);
    g_blk[b * NPAD + n] = a;
}

// ---------------------------------------------------------------------------
// Precompute 5: qbase = graph@Wfix + bfix + bstep + first@Wstep[:128]
// ---------------------------------------------------------------------------
__global__ void qbase_kernel(const float* __restrict__ g,
                             const float* __restrict__ node,
                             const float* __restrict__ Wfix,
                             const float* __restrict__ bfix,
                             const float* __restrict__ Wstep,
                             const float* __restrict__ bstep) {
    const int b = blockIdx.x, e = threadIdx.x;
    __shared__ float gs[EE], fs[EE];
    gs[e] = g[b * EE + e];
    fs[e] = node[(size_t)b * NTOK * EE + e];
    __syncthreads();
    float a = bfix[e] + bstep[e];
    #pragma unroll 4
    for (int k = 0; k < EE; ++k) {
        a += gs[k] * Wfix[(size_t)k * EE + e];
        a += fs[k] * Wstep[(size_t)k * EE + e];
    }
    g_qbase[b * EE + e] = a;
}

__device__ __forceinline__ float tanh_fast(float x) {
    float r;
    asm("tanh.approx.f32 %0, %1;" : "=f"(r) : "f"(x));
    return r;
}

__device__ __forceinline__ __half2 fp8x2_to_h2(unsigned short v) {
    __half2 h;
    asm("cvt.rn.f16x2.e4m3x2 %0, %1;" : "=r"(*(unsigned*)&h) : "h"(v));
    return h;
}

// 16 e4m3 (uint4) dot 16 halves (as 8 x half2), half2 accumulation
__device__ __forceinline__ float dot16_fp8(const uint4 r, const __half2* __restrict__ qh) {
    __half2 acc = __float2half2_rn(0.f);
    acc = __hfma2(fp8x2_to_h2((unsigned short)(r.x)),       qh[0], acc);
    acc = __hfma2(fp8x2_to_h2((unsigned short)(r.x >> 16)), qh[1], acc);
    acc = __hfma2(fp8x2_to_h2((unsigned short)(r.y)),       qh[2], acc);
    acc = __hfma2(fp8x2_to_h2((unsigned short)(r.y >> 16)), qh[3], acc);
    acc = __hfma2(fp8x2_to_h2((unsigned short)(r.z)),       qh[4], acc);
    acc = __hfma2(fp8x2_to_h2((unsigned short)(r.z >> 16)), qh[5], acc);
    acc = __hfma2(fp8x2_to_h2((unsigned short)(r.w)),       qh[6], acc);
    acc = __hfma2(fp8x2_to_h2((unsigned short)(r.w >> 16)), qh[7], acc);
    return __low2float(acc) + __high2float(acc);
}

// ---------------------------------------------------------------------------
// Persistent decode loop with periodic active-token compaction.
// ---------------------------------------------------------------------------
__global__ void __launch_bounds__(1024, 1)
decode_loop(float* __restrict__ out) {
    const int b    = blockIdx.x;
    const int t    = threadIdx.x;
    const int warp = t >> 5, lane = t & 31;

    __shared__ __align__(16) float smp[HH * NPAD];   // 32 KB
    __shared__ float sm_blk[NPAD];                   // 4 KB
    __shared__ int   sm_idx[NPAD];                   // 4 KB
    __shared__ float sm_wred[32 * 9];
    __shared__ int   sm_iwred[32];
    __shared__ __align__(16) __half sm_qh[EE];       // q as halves
    __shared__ __align__(16) __half sm_ctxh[EE];     // ctx as halves
    __shared__ float sm_qbase[EE];
    __shared__ unsigned char sm_mask[NPAD];
    __shared__ int   sm_cbase[32];
    __shared__ int   sm_newM;

    if (t < EE) sm_qbase[t] = g_qbase[b * EE + t];
    sm_blk[t]  = g_blk[b * NPAD + t];
    sm_idx[t]  = t;
    sm_mask[t] = (t == 0 || t >= NTOK) ? 1 : 0;
    __syncthreads();

    const uint4* kq = g_K16 + (size_t)b * 8 * NPAD + t;
    const uint4* gq = g_G16 + (size_t)b * 8 * NPAD + t;
    int   cur   = 0;
    float total = 0.f;
    int   M_pad = NPAD;    // active slots (rounded to 32)
    int   nch   = NPAD / 32;

    #pragma unroll 1
    for (int step = 0; step < NTOK - 1; ++step) {
        // ---- q row (as halves): qbase + SK[cur] ----
        if (t < EE)
            sm_qh[t] = __float2half(sm_qbase[t] + g_SK[((size_t)b * NTOK + cur) * EE + t]);
        __syncthreads();   // S1 (publishes q + mask/compaction from prev iter)

        // ---- C: scores via half2 fp8 dots, p = exp (no max-shift) ----
        const bool msk = sm_mask[t];
        if (t < M_pad) {
            #pragma unroll
            for (int h = 0; h < HH; ++h) {
                const float a = dot16_fp8(kq[(size_t)h * NPAD],
                                          (const __half2*)(sm_qh + h * 16));
                smp[h * NPAD + t] = msk ? 0.f : __expf(a * SC_C);
            }
        }
        __syncthreads();   // S2

        // ---- D: ctx; warp w owns quad w (e = 4w..4w+3), h = w>>2;
        //      fp32 accumulation, per-head softmax sum folded in ----
        {
            const int h = warp >> 2;
            float a0 = 0.f, a1 = 0.f, a2 = 0.f, a3 = 0.f, ps = 0.f;
            const unsigned* vt = g_V4u + ((size_t)b * 32 + warp) * NPAD;
            const float* pp = smp + h * NPAD;
            #pragma unroll 4
            for (int n = lane; n < M_pad; n += 32) {
                const unsigned r = vt[n];
                const float p = pp[n];
                const float2 f01 = __half22float2(fp8x2_to_h2((unsigned short)r));
                const float2 f23 = __half22float2(fp8x2_to_h2((unsigned short)(r >> 16)));
                ps += p;
                a0 += p * f01.x; a1 += p * f01.y; a2 += p * f23.x; a3 += p * f23.y;
            }
            #pragma unroll
            for (int o = 16; o > 0; o >>= 1) {
                a0 += __shfl_xor_sync(~0u, a0, o);
                a1 += __shfl_xor_sync(~0u, a1, o);
                a2 += __shfl_xor_sync(~0u, a2, o);
                a3 += __shfl_xor_sync(~0u, a3, o);
                ps += __shfl_xor_sync(~0u, ps, o);
            }
            if (lane == 0) {
                const float inv = 1.0f / (ps * FP8S);   // undo V fp8 scale
                sm_ctxh[warp * 4 + 0] = __float2half(a0 * inv);
                sm_ctxh[warp * 4 + 1] = __float2half(a1 * inv);
                sm_ctxh[warp * 4 + 2] = __float2half(a2 * inv);
                sm_ctxh[warp * 4 + 3] = __float2half(a3 * inv);
            }
        }
        __syncthreads();   // S3

        // ---- F: logits = ctx.G/256 + blk; fused argmax + sum exp ----
        {
            float mv = NEGV, s = 0.f;
            int   mi = t;
            if (t < M_pad) {
                float d = 0.f;
                #pragma unroll
                for (int o8 = 0; o8 < 8; ++o8)
                    d += dot16_fp8(gq[(size_t)o8 * NPAD],
                                   (const __half2*)(sm_ctxh + o8 * 16));
                const float a = sm_blk[t] + d * (1.0f / FP8S);
                if (!msk) {
                    mv = a;
                    s  = __expf(tanh_fast(a * SCALE) * 10.0f);
                }
                #pragma unroll
                for (int o = 16; o > 0; o >>= 1) {
                    const float ov = __shfl_xor_sync(~0u, mv, o);
                    const int   oi = __shfl_xor_sync(~0u, mi, o);
                    s += __shfl_xor_sync(~0u, s, o);
                    if (ov > mv || (ov == mv && oi < mi)) { mv = ov; mi = oi; }
                }
            }
            if (lane == 0) {
                sm_wred[warp * 9 + 0] = mv;
                sm_wred[warp * 9 + 1] = s;
                sm_iwred[warp] = mi;
            }
        }
        __syncthreads();   // S4

        // ---- final reduce, redundant in every warp ----
        {
            float mv = sm_wred[lane * 9 + 0];
            float s  = sm_wred[lane * 9 + 1];
            int   mi = sm_iwred[lane];
            #pragma unroll
            for (int o = 16; o > 0; o >>= 1) {
                const float ov = __shfl_xor_sync(~0u, mv, o);
                const int   oi = __shfl_xor_sync(~0u, mi, o);
                s += __shfl_xor_sync(~0u, s, o);
                if (ov > mv || (ov == mv && oi < mi)) { mv = ov; mi = oi; }
            }
            if (t == 0) {
                total += tanhf(mv * SCALE) * 10.0f - logf(s);  // precise winner
                sm_mask[mi] = 1;
            }
            cur = sm_idx[mi];
        }

        // ---- periodic stable compaction of active tokens ----
        if (((step + 1) & 63) == 0) {
            __syncthreads();                 // CS1
            if (warp == 0) {
                int cnt = 0;
                if (lane < nch) {
                    const unsigned char* mp = sm_mask + lane * 32;
                    #pragma unroll
                    for (int j = 0; j < 32; ++j) cnt += (mp[j] == 0);
                }
                int inc = cnt;
                #pragma unroll
                for (int o = 1; o < 32; o <<= 1) {
                    const int v = __shfl_up_sync(~0u, inc, o);
                    if (lane >= o) inc += v;
                }
                if (lane < nch) sm_cbase[lane] = inc - cnt;
                if (lane == nch - 1) sm_newM = inc;
            }
            __syncthreads();                 // CS2
            {
                // rows 0..7: K16 (uint4), 8..15: G16 (uint4), 16..47: V4u (u32)
                for (int rr = warp; rr < 48; rr += 32) {
                    if (rr < 16) {
                        uint4* row = (rr < 8 ? g_K16 + ((size_t)b * 8 + rr) * NPAD
                                             : g_G16 + ((size_t)b * 8 + rr - 8) * NPAD);
                        for (int c = 0; c < nch; ++c) {
                            const int n = c * 32 + lane;
                            const uint4 v = row[n];
                            const bool keep = (sm_mask[n] == 0);
                            const unsigned bal = __ballot_sync(~0u, keep);
                            if (keep)
                                row[sm_cbase[c] + __popc(bal & ((1u << lane) - 1))] = v;
                        }
                    } else {
                        unsigned* row = g_V4u + ((size_t)b * 32 + rr - 16) * NPAD;
                        for (int c = 0; c < nch; ++c) {
                            const int n = c * 32 + lane;
                            const unsigned v = row[n];
                            const bool keep = (sm_mask[n] == 0);
                            const unsigned bal = __ballot_sync(~0u, keep);
                            if (keep)
                                row[sm_cbase[c] + __popc(bal & ((1u << lane) - 1))] = v;
                        }
                    }
                }
                if (warp == 0) {
                    for (int c = 0; c < nch; ++c) {
                        const int n = c * 32 + lane;
                        const float v = sm_blk[n];
                        const bool keep = (sm_mask[n] == 0);
                        const unsigned bal = __ballot_sync(~0u, keep);
                        if (keep)
                            sm_blk[sm_cbase[c] + __popc(bal & ((1u << lane) - 1))] = v;
                    }
                }
                if (warp == 1) {
                    for (int c = 0; c < nch; ++c) {
                        const int n = c * 32 + lane;
                        const int v = sm_idx[n];
                        const bool keep = (sm_mask[n] == 0);
                        const unsigned bal = __ballot_sync(~0u, keep);
                        if (keep)
                            sm_idx[sm_cbase[c] + __popc(bal & ((1u << lane) - 1))] = v;
                    }
                }
            }
            __syncthreads();                 // CS3
            const int M = sm_newM;
            M_pad = (M + 31) & ~31;
            nch   = M_pad >> 5;
            sm_mask[t] = (t >= M) ? 1 : 0;
        }
    }

    if (t == 0) out[b] = total;
}

// ---------------------------------------------------------------------------
extern "C" void kernel_launch(void* const* d_in, const int* in_sizes, int n_in,
                              void* d_out, int out_size) {
    const float* node  = (const float*)d_in[0];
    const float* graph = (const float*)d_in[1];
    const float* Wqkv  = (const float*)d_in[2];
    const float* bqkv  = (const float*)d_in[3];
    const float* Wfix  = (const float*)d_in[4];
    const float* bfix  = (const float*)d_in[5];
    const float* Wstep = (const float*)d_in[6];
    const float* bstep = (const float*)d_in[7];
    const float* Wmlp  = (const float*)d_in[8];
    const float* bmlp  = (const float*)d_in[9];
    float* out = (float*)d_out;

    dim3 blk2(16, 16);
    qkv_gemm<<<dim3(6, 16, BB), blk2>>>(node, Wqkv, bqkv);
    sk_gemm <<<dim3(2, 16, BB), blk2>>>(node, Wstep);
    g_gemm  <<<dim3(2, 16, BB), blk2>>>(Wmlp);
    blk_kernel <<<BB, NPAD>>>(bmlp);
    qbase_kernel<<<BB, EE>>>(graph, node, Wfix, bfix, Wstep, bstep);
    decode_loop<<<BB, 1024>>>(out);
}

// round 11
// speedup vs baseline: 1.7449x; 1.0359x over previous
#include <cuda_runtime.h>
#include <cuda_bf16.h>
#include <cuda_fp16.h>
#include <cuda_fp8.h>
#include <math.h>

#define BB   128
#define NTOK 1000
#define NPAD 1024
#define EE   128
#define HH   8
#define NEGV (-1000000000.0f)
#define SCALE 0.25f
#define FP8S 256.0f            // storage scale for e4m3
#define SC_C (0.25f / 256.0f)  // score scale incl. fp8 unscale
#define VSMEM_BYTES (32 * NPAD * 4)   // 128 KB

// K, G: 16-feature interleave (one head / one c-group per uint4 of e4m3):
//   (b,e,n) -> fp8 byte ((b*8 + (e>>4))*NPAD + n)*16 + (e&15)
// V: 4-feature quads of e4m3: (b,e,n) -> fp8 byte ((b*32 + (e>>2))*NPAD + n)*4 + (e&3)
__device__ uint4    g_K16[BB * 8 * NPAD];
__device__ uint4    g_G16[BB * 8 * NPAD];
__device__ unsigned g_V4u[BB * 32 * NPAD];
__device__ __nv_bfloat16 g_LKp[BB * EE * NPAD];
__device__ float g_SK   [(size_t)BB * NTOK * EE];   // node @ Wstep[128:]
__device__ float g_qbase[BB * EE];
__device__ float g_blk  [BB * NPAD];                // bmlp . LK[:,n]

static __device__ __forceinline__ unsigned char to_fp8(float v) {
    return (unsigned char)__nv_cvt_float_to_fp8(v * FP8S, __NV_SATFINITE, __NV_E4M3);
}

// ---------------------------------------------------------------------------
// Precompute 1: qkv = node @ Wqkv + bqkv -> K16(fp8) / V4u(fp8) / LKp(bf16)
// ---------------------------------------------------------------------------
__global__ void qkv_gemm(const float* __restrict__ node,
                         const float* __restrict__ W,
                         const float* __restrict__ bias) {
    __shared__ float As[16][64];
    __shared__ float Bs[16][64];
    const int b  = blockIdx.z;
    const int n0 = blockIdx.y * 64;
    const int e0 = blockIdx.x * 64;
    const int tx = threadIdx.x, ty = threadIdx.y;
    const int t  = ty * 16 + tx;
    const int an = t >> 2, ak = (t & 3) * 4;
    const int bk = t >> 4, be = (t & 15) * 4;

    float acc[4][4] = {};
    for (int k0 = 0; k0 < 128; k0 += 16) {
        float4 av;
        const int n = n0 + an;
        if (n < NTOK) av = *(const float4*)&node[((size_t)b * NTOK + n) * EE + k0 + ak];
        else          av = make_float4(0.f, 0.f, 0.f, 0.f);
        As[ak + 0][an] = av.x; As[ak + 1][an] = av.y;
        As[ak + 2][an] = av.z; As[ak + 3][an] = av.w;
        *(float4*)&Bs[bk][be] = *(const float4*)&W[(size_t)(k0 + bk) * 384 + e0 + be];
        __syncthreads();
        #pragma unroll
        for (int kk = 0; kk < 16; ++kk) {
            float ar[4], br[4];
            #pragma unroll
            for (int i = 0; i < 4; ++i) ar[i] = As[kk][ty * 4 + i];
            #pragma unroll
            for (int j = 0; j < 4; ++j) br[j] = Bs[kk][tx * 4 + j];
            #pragma unroll
            for (int i = 0; i < 4; ++i)
                #pragma unroll
                for (int j = 0; j < 4; ++j) acc[i][j] += ar[i] * br[j];
        }
        __syncthreads();
    }

    unsigned char* K = (unsigned char*)g_K16;
    unsigned char* V = (unsigned char*)g_V4u;
    #pragma unroll
    for (int i = 0; i < 4; ++i) {
        const int n = n0 + ty * 4 + i;
        if (n >= NTOK) continue;
        #pragma unroll
        for (int j = 0; j < 4; ++j) {
            const int e3 = e0 + tx * 4 + j;
            const float v = acc[i][j] + bias[e3];
            if (e3 < 128) {
                const int e = e3;
                K[((size_t)(b * 8 + (e >> 4)) * NPAD + n) * 16 + (e & 15)] = to_fp8(v);
            } else if (e3 < 256) {
                const int e = e3 - 128;
                V[((size_t)(b * 32 + (e >> 2)) * NPAD + n) * 4 + (e & 3)] = to_fp8(v);
            } else {
                const int e = e3 - 256;
                g_LKp[(size_t)(b * EE + e) * NPAD + n] = __float2bfloat16(v);
            }
        }
    }
}

// ---------------------------------------------------------------------------
// Precompute 2: SK[b][n][e] = node[b,n] @ Wstep[128:256]  (fp32)
// ---------------------------------------------------------------------------
__global__ void sk_gemm(const float* __restrict__ node,
                        const float* __restrict__ Wstep) {
    __shared__ float As[16][64];
    __shared__ float Bs[16][64];
    const float* W2 = Wstep + 128 * EE;
    const int b  = blockIdx.z;
    const int n0 = blockIdx.y * 64;
    const int e0 = blockIdx.x * 64;
    const int tx = threadIdx.x, ty = threadIdx.y;
    const int t  = ty * 16 + tx;
    const int an = t >> 2, ak = (t & 3) * 4;
    const int bk = t >> 4, be = (t & 15) * 4;

    float acc[4][4] = {};
    for (int k0 = 0; k0 < 128; k0 += 16) {
        float4 av;
        const int n = n0 + an;
        if (n < NTOK) av = *(const float4*)&node[((size_t)b * NTOK + n) * EE + k0 + ak];
        else          av = make_float4(0.f, 0.f, 0.f, 0.f);
        As[ak + 0][an] = av.x; As[ak + 1][an] = av.y;
        As[ak + 2][an] = av.z; As[ak + 3][an] = av.w;
        *(float4*)&Bs[bk][be] = *(const float4*)&W2[(size_t)(k0 + bk) * EE + e0 + be];
        __syncthreads();
        #pragma unroll
        for (int kk = 0; kk < 16; ++kk) {
            float ar[4], br[4];
            #pragma unroll
            for (int i = 0; i < 4; ++i) ar[i] = As[kk][ty * 4 + i];
            #pragma unroll
            for (int j = 0; j < 4; ++j) br[j] = Bs[kk][tx * 4 + j];
            #pragma unroll
            for (int i = 0; i < 4; ++i)
                #pragma unroll
                for (int j = 0; j < 4; ++j) acc[i][j] += ar[i] * br[j];
        }
        __syncthreads();
    }
    #pragma unroll
    for (int i = 0; i < 4; ++i) {
        const int n = n0 + ty * 4 + i;
        if (n >= NTOK) continue;
        #pragma unroll
        for (int j = 0; j < 4; ++j)
            g_SK[((size_t)b * NTOK + n) * EE + e0 + tx * 4 + j] = acc[i][j];
    }
}

// ---------------------------------------------------------------------------
// Precompute 3: G[b][c][n] = Wmlp[c][:] . LK[b][:][n]  -> 16-interleaved fp8
// ---------------------------------------------------------------------------
__global__ void g_gemm(const float* __restrict__ Wmlp) {
    __shared__ float As[16][64];   // [e][c]
    __shared__ float Bs[16][64];   // [e][n]
    const int b  = blockIdx.z;
    const int n0 = blockIdx.y * 64;
    const int c0 = blockIdx.x * 64;
    const int tx = threadIdx.x, ty = threadIdx.y;
    const int t  = ty * 16 + tx;
    const int ac = t >> 2, ae = (t & 3) * 4;
    const int bk = t >> 4, bn = (t & 15) * 4;

    float acc[4][4] = {};
    for (int k0 = 0; k0 < 128; k0 += 16) {
        const float4 av = *(const float4*)&Wmlp[(size_t)(c0 + ac) * EE + k0 + ae];
        As[ae + 0][ac] = av.x; As[ae + 1][ac] = av.y;
        As[ae + 2][ac] = av.z; As[ae + 3][ac] = av.w;
        const uint2 r = *(const uint2*)&g_LKp[(size_t)(b * EE + k0 + bk) * NPAD + n0 + bn];
        const float2 v0 = __bfloat1622float2(*(const __nv_bfloat162*)&r.x);
        const float2 v1 = __bfloat1622float2(*(const __nv_bfloat162*)&r.y);
        Bs[bk][bn + 0] = v0.x; Bs[bk][bn + 1] = v0.y;
        Bs[bk][bn + 2] = v1.x; Bs[bk][bn + 3] = v1.y;
        __syncthreads();
        #pragma unroll
        for (int kk = 0; kk < 16; ++kk) {
            float ar[4], br[4];
            #pragma unroll
            for (int i = 0; i < 4; ++i) ar[i] = As[kk][ty * 4 + i];
            #pragma unroll
            for (int j = 0; j < 4; ++j) br[j] = Bs[kk][tx * 4 + j];
            #pragma unroll
            for (int i = 0; i < 4; ++i)
                #pragma unroll
                for (int j = 0; j < 4; ++j) acc[i][j] += ar[i] * br[j];
        }
        __syncthreads();
    }
    unsigned char* G = (unsigned char*)g_G16;
    #pragma unroll
    for (int i = 0; i < 4; ++i) {
        const int c = c0 + ty * 4 + i;
        #pragma unroll
        for (int j = 0; j < 4; ++j) {
            const int n = n0 + tx * 4 + j;
            G[((size_t)(b * 8 + (c >> 4)) * NPAD + n) * 16 + (c & 15)] = to_fp8(acc[i][j]);
        }
    }
}

// ---------------------------------------------------------------------------
// Precompute 4: blk[b][n] = bmlp . LK[b][:][n]
// ---------------------------------------------------------------------------
__global__ void blk_kernel(const float* __restrict__ bmlp) {
    const int b = blockIdx.x, n = threadIdx.x;
    __shared__ float bm[EE];
    if (n < EE) bm[n] = bmlp[n];
    __syncthreads();
    float a = 0.f;
    #pragma unroll 8
    for (int e = 0; e < EE; ++e)
        a += bm[e] * __bfloat162float(g_LKp[(size_t)(b * EE + e) * NPAD + n]);
    g_blk[b * NPAD + n] = a;
}

// ---------------------------------------------------------------------------
// Precompute 5: qbase = graph@Wfix + bfix + bstep + first@Wstep[:128]
// ---------------------------------------------------------------------------
__global__ void qbase_kernel(const float* __restrict__ g,
                             const float* __restrict__ node,
                             const float* __restrict__ Wfix,
                             const float* __restrict__ bfix,
                             const float* __restrict__ Wstep,
                             const float* __restrict__ bstep) {
    const int b = blockIdx.x, e = threadIdx.x;
    __shared__ float gs[EE], fs[EE];
    gs[e] = g[b * EE + e];
    fs[e] = node[(size_t)b * NTOK * EE + e];
    __syncthreads();
    float a = bfix[e] + bstep[e];
    #pragma unroll 4
    for (int k = 0; k < EE; ++k) {
        a += gs[k] * Wfix[(size_t)k * EE + e];
        a += fs[k] * Wstep[(size_t)k * EE + e];
    }
    g_qbase[b * EE + e] = a;
}

__device__ __forceinline__ float tanh_fast(float x) {
    float r;
    asm("tanh.approx.f32 %0, %1;" : "=f"(r) : "f"(x));
    return r;
}

__device__ __forceinline__ __half2 fp8x2_to_h2(unsigned short v) {
    __half2 h;
    asm("cvt.rn.f16x2.e4m3x2 %0, %1;" : "=r"(*(unsigned*)&h) : "h"(v));
    return h;
}

// 16 e4m3 (uint4) dot 16 halves (as 8 x half2), half2 accumulation
__device__ __forceinline__ float dot16_fp8(const uint4 r, const __half2* __restrict__ qh) {
    __half2 acc = __float2half2_rn(0.f);
    acc = __hfma2(fp8x2_to_h2((unsigned short)(r.x)),       qh[0], acc);
    acc = __hfma2(fp8x2_to_h2((unsigned short)(r.x >> 16)), qh[1], acc);
    acc = __hfma2(fp8x2_to_h2((unsigned short)(r.y)),       qh[2], acc);
    acc = __hfma2(fp8x2_to_h2((unsigned short)(r.y >> 16)), qh[3], acc);
    acc = __hfma2(fp8x2_to_h2((unsigned short)(r.z)),       qh[4], acc);
    acc = __hfma2(fp8x2_to_h2((unsigned short)(r.z >> 16)), qh[5], acc);
    acc = __hfma2(fp8x2_to_h2((unsigned short)(r.w)),       qh[6], acc);
    acc = __hfma2(fp8x2_to_h2((unsigned short)(r.w >> 16)), qh[7], acc);
    return __low2float(acc) + __high2float(acc);
}

// ---------------------------------------------------------------------------
// Persistent decode loop; V resident in shared memory for the whole decode.
// ---------------------------------------------------------------------------
__global__ void __launch_bounds__(1024, 1)
decode_loop(float* __restrict__ out) {
    const int b    = blockIdx.x;
    const int t    = threadIdx.x;
    const int warp = t >> 5, lane = t & 31;

    extern __shared__ unsigned v_s[];                // 32 rows x NPAD fp8-quads (128 KB)

    __shared__ __align__(16) float smp[HH * NPAD];   // 32 KB
    __shared__ float sm_blk[NPAD];                   // 4 KB
    __shared__ int   sm_idx[NPAD];                   // 4 KB
    __shared__ float sm_wred[32 * 9];
    __shared__ int   sm_iwred[32];
    __shared__ __align__(16) __half sm_qh[EE];       // q as halves
    __shared__ __align__(16) __half sm_ctxh[EE];     // ctx as halves
    __shared__ float sm_qbase[EE];
    __shared__ unsigned char sm_mask[NPAD];
    __shared__ int   sm_cbase[32];
    __shared__ int   sm_newM;

    if (t < EE) sm_qbase[t] = g_qbase[b * EE + t];
    sm_blk[t]  = g_blk[b * NPAD + t];
    sm_idx[t]  = t;
    sm_mask[t] = (t == 0 || t >= NTOK) ? 1 : 0;

    // copy V row for this warp into smem (one-time, 128 KB)
    {
        const uint4* src = (const uint4*)(g_V4u + ((size_t)b * 32 + warp) * NPAD);
        uint4* dst = (uint4*)(v_s + warp * NPAD);
        for (int i = lane; i < NPAD / 4; i += 32) dst[i] = src[i];
    }
    __syncthreads();

    const uint4* kq = g_K16 + (size_t)b * 8 * NPAD + t;
    const uint4* gq = g_G16 + (size_t)b * 8 * NPAD + t;
    int   cur   = 0;
    float total = 0.f;
    int   M_pad = NPAD;    // active slots (rounded to 32)
    int   nch   = NPAD / 32;

    #pragma unroll 1
    for (int step = 0; step < NTOK - 1; ++step) {
        // ---- q row (as halves): qbase + SK[cur] ----
        if (t < EE)
            sm_qh[t] = __float2half(sm_qbase[t] + g_SK[((size_t)b * NTOK + cur) * EE + t]);
        __syncthreads();   // S1 (publishes q + mask/compaction from prev iter)

        // ---- C: scores via half2 fp8 dots, p = exp (no max-shift) ----
        const bool msk = sm_mask[t];
        if (t < M_pad) {
            #pragma unroll
            for (int h = 0; h < HH; ++h) {
                const float a = dot16_fp8(kq[(size_t)h * NPAD],
                                          (const __half2*)(sm_qh + h * 16));
                smp[h * NPAD + t] = msk ? 0.f : __expf(a * SC_C);
            }
        }
        __syncthreads();   // S2

        // ---- D: ctx; warp w owns quad w (e = 4w..4w+3), h = w>>2;
        //      V from smem, 2 tokens per lane, softmax sum folded in ----
        {
            const int h = warp >> 2;
            float a0 = 0.f, a1 = 0.f, a2 = 0.f, a3 = 0.f, ps = 0.f;
            const uint2*  vt2 = (const uint2*)(v_s + warp * NPAD);
            const float2* pp2 = (const float2*)(smp + h * NPAD);
            const int m2 = M_pad >> 1;
            #pragma unroll 4
            for (int n2 = lane; n2 < m2; n2 += 32) {
                const uint2  r  = vt2[n2];          // tokens 2*n2, 2*n2+1
                const float2 p2 = pp2[n2];
                const float2 fA0 = __half22float2(fp8x2_to_h2((unsigned short)r.x));
                const float2 fA1 = __half22float2(fp8x2_to_h2((unsigned short)(r.x >> 16)));
                const float2 fB0 = __half22float2(fp8x2_to_h2((unsigned short)r.y));
                const float2 fB1 = __half22float2(fp8x2_to_h2((unsigned short)(r.y >> 16)));
                ps += p2.x + p2.y;
                a0 += p2.x * fA0.x + p2.y * fB0.x;
                a1 += p2.x * fA0.y + p2.y * fB0.y;
                a2 += p2.x * fA1.x + p2.y * fB1.x;
                a3 += p2.x * fA1.y + p2.y * fB1.y;
            }
            #pragma unroll
            for (int o = 16; o > 0; o >>= 1) {
                a0 += __shfl_xor_sync(~0u, a0, o);
                a1 += __shfl_xor_sync(~0u, a1, o);
                a2 += __shfl_xor_sync(~0u, a2, o);
                a3 += __shfl_xor_sync(~0u, a3, o);
                ps += __shfl_xor_sync(~0u, ps, o);
            }
            if (lane == 0) {
                const float inv = 1.0f / (ps * FP8S);   // undo V fp8 scale
                sm_ctxh[warp * 4 + 0] = __float2half(a0 * inv);
                sm_ctxh[warp * 4 + 1] = __float2half(a1 * inv);
                sm_ctxh[warp * 4 + 2] = __float2half(a2 * inv);
                sm_ctxh[warp * 4 + 3] = __float2half(a3 * inv);
            }
        }
        __syncthreads();   // S3

        // ---- F: logits = ctx.G/256 + blk; fused argmax + sum exp ----
        {
            float mv = NEGV, s = 0.f;
            int   mi = t;
            if (t < M_pad) {
                float d = 0.f;
                #pragma unroll
                for (int o8 = 0; o8 < 8; ++o8)
                    d += dot16_fp8(gq[(size_t)o8 * NPAD],
                                   (const __half2*)(sm_ctxh + o8 * 16));
                const float a = sm_blk[t] + d * (1.0f / FP8S);
                if (!msk) {
                    mv = a;
                    s  = __expf(tanh_fast(a * SCALE) * 10.0f);
                }
                #pragma unroll
                for (int o = 16; o > 0; o >>= 1) {
                    const float ov = __shfl_xor_sync(~0u, mv, o);
                    const int   oi = __shfl_xor_sync(~0u, mi, o);
                    s += __shfl_xor_sync(~0u, s, o);
                    if (ov > mv || (ov == mv && oi < mi)) { mv = ov; mi = oi; }
                }
            }
            if (lane == 0) {
                sm_wred[warp * 9 + 0] = mv;
                sm_wred[warp * 9 + 1] = s;
                sm_iwred[warp] = mi;
            }
        }
        __syncthreads();   // S4

        // ---- final reduce, redundant in every warp ----
        {
            float mv = sm_wred[lane * 9 + 0];
            float s  = sm_wred[lane * 9 + 1];
            int   mi = sm_iwred[lane];
            #pragma unroll
            for (int o = 16; o > 0; o >>= 1) {
                const float ov = __shfl_xor_sync(~0u, mv, o);
                const int   oi = __shfl_xor_sync(~0u, mi, o);
                s += __shfl_xor_sync(~0u, s, o);
                if (ov > mv || (ov == mv && oi < mi)) { mv = ov; mi = oi; }
            }
            if (t == 0) {
                total += tanhf(mv * SCALE) * 10.0f - logf(s);  // precise winner
                sm_mask[mi] = 1;
            }
            cur = sm_idx[mi];
        }

        // ---- periodic stable compaction of active tokens ----
        if (((step + 1) & 63) == 0) {
            __syncthreads();                 // CS1
            if (warp == 0) {
                int cnt = 0;
                if (lane < nch) {
                    const unsigned char* mp = sm_mask + lane * 32;
                    #pragma unroll
                    for (int j = 0; j < 32; ++j) cnt += (mp[j] == 0);
                }
                int inc = cnt;
                #pragma unroll
                for (int o = 1; o < 32; o <<= 1) {
                    const int v = __shfl_up_sync(~0u, inc, o);
                    if (lane >= o) inc += v;
                }
                if (lane < nch) sm_cbase[lane] = inc - cnt;
                if (lane == nch - 1) sm_newM = inc;
            }
            __syncthreads();                 // CS2
            {
                // rows 0..7: K16 (uint4, global), 8..15: G16 (uint4, global),
                // rows 16..47: V rows (unsigned, smem)
                for (int rr = warp; rr < 48; rr += 32) {
                    if (rr < 16) {
                        uint4* row = (rr < 8 ? g_K16 + ((size_t)b * 8 + rr) * NPAD
                                             : g_G16 + ((size_t)b * 8 + rr - 8) * NPAD);
                        for (int c = 0; c < nch; ++c) {
                            const int n = c * 32 + lane;
                            const uint4 v = row[n];
                            const bool keep = (sm_mask[n] == 0);
                            const unsigned bal = __ballot_sync(~0u, keep);
                            if (keep)
                                row[sm_cbase[c] + __popc(bal & ((1u << lane) - 1))] = v;
                        }
                    } else {
                        unsigned* row = v_s + (rr - 16) * NPAD;
                        for (int c = 0; c < nch; ++c) {
                            const int n = c * 32 + lane;
                            const unsigned v = row[n];
                            const bool keep = (sm_mask[n] == 0);
                            const unsigned bal = __ballot_sync(~0u, keep);
                            if (keep)
                                row[sm_cbase[c] + __popc(bal & ((1u << lane) - 1))] = v;
                        }
                    }
                }
                if (warp == 0) {
                    for (int c = 0; c < nch; ++c) {
                        const int n = c * 32 + lane;
                        const float v = sm_blk[n];
                        const bool keep = (sm_mask[n] == 0);
                        const unsigned bal = __ballot_sync(~0u, keep);
                        if (keep)
                            sm_blk[sm_cbase[c] + __popc(bal & ((1u << lane) - 1))] = v;
                    }
                }
                if (warp == 1) {
                    for (int c = 0; c < nch; ++c) {
                        const int n = c * 32 + lane;
                        const int v = sm_idx[n];
                        const bool keep = (sm_mask[n] == 0);
                        const unsigned bal = __ballot_sync(~0u, keep);
                        if (keep)
                            sm_idx[sm_cbase[c] + __popc(bal & ((1u << lane) - 1))] = v;
                    }
                }
            }
            __syncthreads();                 // CS3
            const int M = sm_newM;
            M_pad = (M + 31) & ~31;
            nch   = M_pad >> 5;
            sm_mask[t] = (t >= M) ? 1 : 0;
        }
    }

    if (t == 0) out[b] = total;
}

// ---------------------------------------------------------------------------
extern "C" void kernel_launch(void* const* d_in, const int* in_sizes, int n_in,
                              void* d_out, int out_size) {
    const float* node  = (const float*)d_in[0];
    const float* graph = (const float*)d_in[1];
    const float* Wqkv  = (const float*)d_in[2];
    const float* bqkv  = (const float*)d_in[3];
    const float* Wfix  = (const float*)d_in[4];
    const float* bfix  = (const float*)d_in[5];
    const float* Wstep = (const float*)d_in[6];
    const float* bstep = (const float*)d_in[7];
    const float* Wmlp  = (const float*)d_in[8];
    const float* bmlp  = (const float*)d_in[9];
    float* out = (float*)d_out;

    static int attr_done = 0;
    if (!attr_done) {
        cudaFuncSetAttribute(decode_loop,
                             cudaFuncAttributeMaxDynamicSharedMemorySize, VSMEM_BYTES);
        attr_done = 1;
    }

    dim3 blk2(16, 16);
    qkv_gemm<<<dim3(6, 16, BB), blk2>>>(node, Wqkv, bqkv);
    sk_gemm <<<dim3(2, 16, BB), blk2>>>(node, Wstep);
    g_gemm  <<<dim3(2, 16, BB), blk2>>>(Wmlp);
    blk_kernel <<<BB, NPAD>>>(bmlp);
    qbase_kernel<<<BB, EE>>>(graph, node, Wfix, bfix, Wstep, bstep);
    decode_loop<<<BB, 1024, VSMEM_BYTES>>>(out);
}